// round 1
// baseline (speedup 1.0000x reference)
#include <cuda_runtime.h>
#include <math.h>

#define T_TOK  16384
#define D_EMB  768
#define D_HID  3072
#define N_HEAD 12
#define HD     64
#define N_SEQ  1024
#define N_BATCH 16

// ---------------- scratch (device globals: allocation-free) ----------------
__device__ float g_xn [T_TOK * D_EMB];        // LN output (reused for LN1 and LN2)
__device__ float g_qkv[T_TOK * 3 * D_EMB];    // QKV activations
__device__ float g_ctx[T_TOK * D_EMB];        // attention context
__device__ float g_x1 [T_TOK * D_EMB];        // x + attn branch
__device__ float g_h  [T_TOK * D_HID];        // gelu(fc1)

// ---------------- LayerNorm: one block per token ----------------
__global__ __launch_bounds__(256) void ln_kernel(
    const float* __restrict__ x, const float* __restrict__ g,
    const float* __restrict__ b, float* __restrict__ out)
{
    int row = blockIdx.x;
    const float* xr = x + (size_t)row * D_EMB;
    float sum = 0.f, sq = 0.f;
    for (int i = threadIdx.x; i < D_EMB; i += 256) {
        float v = xr[i]; sum += v; sq += v * v;
    }
    __shared__ float s1[8], s2[8];
    #pragma unroll
    for (int o = 16; o > 0; o >>= 1) {
        sum += __shfl_down_sync(0xffffffffu, sum, o);
        sq  += __shfl_down_sync(0xffffffffu, sq, o);
    }
    int w = threadIdx.x >> 5, l = threadIdx.x & 31;
    if (l == 0) { s1[w] = sum; s2[w] = sq; }
    __syncthreads();
    if (threadIdx.x == 0) {
        float a = 0.f, c = 0.f;
        #pragma unroll
        for (int i = 0; i < 8; i++) { a += s1[i]; c += s2[i]; }
        s1[0] = a * (1.0f / D_EMB);
        s2[0] = c * (1.0f / D_EMB);
    }
    __syncthreads();
    float mu = s1[0];
    float var = s2[0] - mu * mu;
    float rstd = rsqrtf(var + 1e-6f);
    float* orow = out + (size_t)row * D_EMB;
    for (int i = threadIdx.x; i < D_EMB; i += 256)
        orow[i] = (xr[i] - mu) * rstd * g[i] + b[i];
}

// ---------------- SGEMM (NT): C[M,N] = A[M,K] * B[N,K]^T + epilogue -------
// MODE 0: + bias            MODE 1: + bias + res        MODE 2: gelu(+bias)
template <int MODE>
__global__ __launch_bounds__(256) void sgemm_nt(
    const float* __restrict__ A, const float* __restrict__ B,
    const float* __restrict__ bias, const float* __restrict__ res,
    float* __restrict__ C, int M, int N, int K)
{
    __shared__ float As[16][132];
    __shared__ float Bs[16][132];

    int tid = threadIdx.x;
    int m0 = blockIdx.y * 128, n0 = blockIdx.x * 128;
    int lr  = tid >> 2;          // 0..63
    int lc4 = (tid & 3) * 4;     // 0,4,8,12
    const float* Ag = A + (size_t)(m0 + lr) * K + lc4;
    const float* Bg = B + (size_t)(n0 + lr) * K + lc4;
    int ty = tid >> 4, tx = tid & 15;

    float acc[8][8];
    #pragma unroll
    for (int i = 0; i < 8; i++)
        #pragma unroll
        for (int j = 0; j < 8; j++) acc[i][j] = 0.f;

    for (int k0 = 0; k0 < K; k0 += 16) {
        float4 a0 = *(const float4*)(Ag + k0);
        float4 a1 = *(const float4*)(Ag + k0 + (size_t)64 * K);
        float4 b0 = *(const float4*)(Bg + k0);
        float4 b1 = *(const float4*)(Bg + k0 + (size_t)64 * K);
        As[lc4+0][lr]    = a0.x; As[lc4+1][lr]    = a0.y; As[lc4+2][lr]    = a0.z; As[lc4+3][lr]    = a0.w;
        As[lc4+0][lr+64] = a1.x; As[lc4+1][lr+64] = a1.y; As[lc4+2][lr+64] = a1.z; As[lc4+3][lr+64] = a1.w;
        Bs[lc4+0][lr]    = b0.x; Bs[lc4+1][lr]    = b0.y; Bs[lc4+2][lr]    = b0.z; Bs[lc4+3][lr]    = b0.w;
        Bs[lc4+0][lr+64] = b1.x; Bs[lc4+1][lr+64] = b1.y; Bs[lc4+2][lr+64] = b1.z; Bs[lc4+3][lr+64] = b1.w;
        __syncthreads();
        #pragma unroll
        for (int k = 0; k < 16; k++) {
            float a[8], b[8];
            *(float4*)(a)   = *(const float4*)&As[k][ty * 8];
            *(float4*)(a+4) = *(const float4*)&As[k][ty * 8 + 4];
            *(float4*)(b)   = *(const float4*)&Bs[k][tx * 8];
            *(float4*)(b+4) = *(const float4*)&Bs[k][tx * 8 + 4];
            #pragma unroll
            for (int i = 0; i < 8; i++)
                #pragma unroll
                for (int j = 0; j < 8; j++)
                    acc[i][j] += a[i] * b[j];
        }
        __syncthreads();
    }

    #pragma unroll
    for (int i = 0; i < 8; i++) {
        size_t r = (size_t)(m0 + ty * 8 + i);
        float* crow = C + r * N + n0 + tx * 8;
        const float* rrow = (MODE == 1) ? (res + r * N + n0 + tx * 8) : nullptr;
        #pragma unroll
        for (int j = 0; j < 8; j++) {
            float v = acc[i][j] + bias[n0 + tx * 8 + j];
            if (MODE == 1) v += rrow[j];
            if (MODE == 2) v = 0.5f * v * (1.0f + erff(v * 0.70710678118654752f));
            crow[j] = v;
        }
    }
}

// ---------------- Flash attention: 64-query tile per block ----------------
// grid: (N_SEQ/64, N_BATCH*N_HEAD), 256 threads, dynamic smem.
#define LDP 65   // smem pad
__global__ __launch_bounds__(256) void attn_kernel(
    const float* __restrict__ qkv, float* __restrict__ ctx)
{
    extern __shared__ float sm[];
    float* Qs = sm;                 // [64][LDP] natural: Q[r][d]
    float* Ks = Qs + 64 * LDP;      // [64][LDP] natural: K[c][d]
    float* Vs = Ks + 64 * LDP;      // [64][LDP] natural: V[kk][d]
    float* Ss = Vs + 64 * LDP;      // [64][LDP] TRANSPOSED: S[c][r]
    float* row_m = Ss + 64 * LDP;
    float* row_l = row_m + 64;
    float* row_a = row_l + 64;

    int tid = threadIdx.x;
    int bh = blockIdx.y;
    int b = bh / N_HEAD, h = bh % N_HEAD;
    int q0 = blockIdx.x * 64;
    size_t tok_base = (size_t)b * N_SEQ;
    int hoff = h * HD;

    // load Q tile
    for (int it = tid; it < 64 * 16; it += 256) {
        int r = it >> 4, c4 = (it & 15) * 4;
        size_t t = tok_base + q0 + r;
        float4 q = *(const float4*)(qkv + t * 2304 + hoff + c4);
        float* qr = Qs + r * LDP + c4;
        qr[0] = q.x; qr[1] = q.y; qr[2] = q.z; qr[3] = q.w;
    }
    if (tid < 64) { row_m[tid] = -1e30f; row_l[tid] = 0.f; }

    int ty = tid >> 4, tx = tid & 15;
    float o[4][4];
    #pragma unroll
    for (int i = 0; i < 4; i++)
        #pragma unroll
        for (int j = 0; j < 4; j++) o[i][j] = 0.f;
    const float scale = 0.125f;   // Hd^-0.5 = 1/8
    __syncthreads();

    for (int kt = 0; kt < N_SEQ / 64; kt++) {
        // load K, V tiles
        for (int it = tid; it < 64 * 16; it += 256) {
            int r = it >> 4, c4 = (it & 15) * 4;
            size_t t = tok_base + kt * 64 + r;
            float4 kk4 = *(const float4*)(qkv + t * 2304 + D_EMB + hoff + c4);
            float4 vv4 = *(const float4*)(qkv + t * 2304 + 2 * D_EMB + hoff + c4);
            float* kr = Ks + r * LDP + c4;
            float* vr = Vs + r * LDP + c4;
            kr[0] = kk4.x; kr[1] = kk4.y; kr[2] = kk4.z; kr[3] = kk4.w;
            vr[0] = vv4.x; vr[1] = vv4.y; vr[2] = vv4.z; vr[3] = vv4.w;
        }
        __syncthreads();

        // S = Q K^T  (each thread: rows 4ty..+3 x cols 4tx..+3)
        float s[4][4];
        #pragma unroll
        for (int i = 0; i < 4; i++)
            #pragma unroll
            for (int j = 0; j < 4; j++) s[i][j] = 0.f;
        #pragma unroll 8
        for (int d = 0; d < 64; d++) {
            float qa[4], kb[4];
            #pragma unroll
            for (int i = 0; i < 4; i++) qa[i] = Qs[(ty * 4 + i) * LDP + d];
            #pragma unroll
            for (int j = 0; j < 4; j++) kb[j] = Ks[(tx * 4 + j) * LDP + d];
            #pragma unroll
            for (int i = 0; i < 4; i++)
                #pragma unroll
                for (int j = 0; j < 4; j++) s[i][j] += qa[i] * kb[j];
        }
        // store transposed + scaled: Ss[c][r]
        #pragma unroll
        for (int i = 0; i < 4; i++)
            #pragma unroll
            for (int j = 0; j < 4; j++)
                Ss[(tx * 4 + j) * LDP + ty * 4 + i] = s[i][j] * scale;
        __syncthreads();

        // online softmax: thread tid handles query row tid (reads Ss columns)
        if (tid < 64) {
            int r = tid;
            float m = row_m[r];
            #pragma unroll 8
            for (int c = 0; c < 64; c++) m = fmaxf(m, Ss[c * LDP + r]);
            float l = 0.f;
            #pragma unroll 8
            for (int c = 0; c < 64; c++) {
                float p = __expf(Ss[c * LDP + r] - m);
                Ss[c * LDP + r] = p;
                l += p;
            }
            float alpha = __expf(row_m[r] - m);
            row_a[r] = alpha;
            row_l[r] = row_l[r] * alpha + l;
            row_m[r] = m;
        }
        __syncthreads();

        // O = O*alpha + P V
        float al[4];
        #pragma unroll
        for (int i = 0; i < 4; i++) al[i] = row_a[ty * 4 + i];
        #pragma unroll
        for (int i = 0; i < 4; i++)
            #pragma unroll
            for (int j = 0; j < 4; j++) o[i][j] *= al[i];
        #pragma unroll 8
        for (int kk = 0; kk < 64; kk++) {
            float p[4], v[4];
            #pragma unroll
            for (int i = 0; i < 4; i++) p[i] = Ss[kk * LDP + ty * 4 + i];
            #pragma unroll
            for (int j = 0; j < 4; j++) v[j] = Vs[kk * LDP + tx * 4 + j];
            #pragma unroll
            for (int i = 0; i < 4; i++)
                #pragma unroll
                for (int j = 0; j < 4; j++) o[i][j] += p[i] * v[j];
        }
        __syncthreads();
    }

    // write ctx[t, h*64 + c] = O / l
    #pragma unroll
    for (int i = 0; i < 4; i++) {
        int r = ty * 4 + i;
        float inv = 1.0f / row_l[r];
        size_t t = tok_base + q0 + r;
        float* orow = ctx + t * D_EMB + hoff + tx * 4;
        #pragma unroll
        for (int j = 0; j < 4; j++) orow[j] = o[i][j] * inv;
    }
}

// ---------------- host launcher ----------------
extern "C" void kernel_launch(void* const* d_in, const int* in_sizes, int n_in,
                              void* d_out, int out_size)
{
    const float* x      = (const float*)d_in[0];
    const float* ln1_g  = (const float*)d_in[1];
    const float* ln1_b  = (const float*)d_in[2];
    const float* qkv_w  = (const float*)d_in[3];
    const float* qkv_b  = (const float*)d_in[4];
    const float* proj_w = (const float*)d_in[5];
    const float* proj_b = (const float*)d_in[6];
    const float* ln2_g  = (const float*)d_in[7];
    const float* ln2_b  = (const float*)d_in[8];
    const float* fc1_w  = (const float*)d_in[9];
    const float* fc1_b  = (const float*)d_in[10];
    const float* fc2_w  = (const float*)d_in[11];
    const float* fc2_b  = (const float*)d_in[12];
    float* out = (float*)d_out;

    float *p_xn, *p_qkv, *p_ctx, *p_x1, *p_h;
    cudaGetSymbolAddress((void**)&p_xn,  g_xn);
    cudaGetSymbolAddress((void**)&p_qkv, g_qkv);
    cudaGetSymbolAddress((void**)&p_ctx, g_ctx);
    cudaGetSymbolAddress((void**)&p_x1,  g_x1);
    cudaGetSymbolAddress((void**)&p_h,   g_h);

    const int attn_smem = (4 * 64 * LDP + 3 * 64) * (int)sizeof(float);
    cudaFuncSetAttribute(attn_kernel, cudaFuncAttributeMaxDynamicSharedMemorySize, attn_smem);

    // 1. LN1
    ln_kernel<<<T_TOK, 256>>>(x, ln1_g, ln1_b, p_xn);
    // 2. QKV = xn @ qkv_w^T + b   [16384, 2304]
    sgemm_nt<0><<<dim3(2304 / 128, T_TOK / 128), 256>>>(p_xn, qkv_w, qkv_b, nullptr,
                                                        p_qkv, T_TOK, 2304, D_EMB);
    // 3. flash attention -> ctx [16384, 768]
    attn_kernel<<<dim3(N_SEQ / 64, N_BATCH * N_HEAD), 256, attn_smem>>>(p_qkv, p_ctx);
    // 4. x1 = x + ctx @ proj_w^T + proj_b
    sgemm_nt<1><<<dim3(D_EMB / 128, T_TOK / 128), 256>>>(p_ctx, proj_w, proj_b, x,
                                                         p_x1, T_TOK, D_EMB, D_EMB);
    // 5. LN2
    ln_kernel<<<T_TOK, 256>>>(p_x1, ln2_g, ln2_b, p_xn);
    // 6. h = gelu(xn @ fc1_w^T + fc1_b)   [16384, 3072]
    sgemm_nt<2><<<dim3(D_HID / 128, T_TOK / 128), 256>>>(p_xn, fc1_w, fc1_b, nullptr,
                                                         p_h, T_TOK, D_HID, D_EMB);
    // 7. out = x1 + h @ fc2_w^T + fc2_b
    sgemm_nt<1><<<dim3(D_EMB / 128, T_TOK / 128), 256>>>(p_h, fc2_w, fc2_b, p_x1,
                                                         out, T_TOK, D_EMB, D_HID);
}

// round 3
// speedup vs baseline: 2.1654x; 2.1654x over previous
#include <cuda_runtime.h>
#include <math.h>
#include <stdint.h>

#define T_TOK   16384
#define D_EMB   768
#define D_HID   3072
#define N_HEAD  12
#define HD      64
#define N_SEQ   1024
#define N_BATCH 16

// ---------------- scratch (device globals: allocation-free) ----------------
__device__ float g_xn [T_TOK * D_EMB];
__device__ float g_qkv[T_TOK * 3 * D_EMB];
__device__ float g_ctx[T_TOK * D_EMB];
__device__ float g_x1 [T_TOK * D_EMB];
__device__ float g_h  [T_TOK * D_HID];
// tf32-rounded weights
__device__ float g_wq[3 * D_EMB * D_EMB];
__device__ float g_wp[D_EMB * D_EMB];
__device__ float g_w1[D_HID * D_EMB];
__device__ float g_w2[D_EMB * D_HID];

// ---------------- helpers ----------------
__device__ __forceinline__ float tf32r(float x) {
    float y; asm("cvt.rna.tf32.f32 %0, %1;" : "=f"(y) : "f"(x)); return y;
}
__device__ __forceinline__ uint32_t s2u(const void* p) {
    uint32_t a;
    asm("{ .reg .u64 t; cvta.to.shared.u64 t, %1; cvt.u32.u64 %0, t; }" : "=r"(a) : "l"(p));
    return a;
}
__device__ __forceinline__ void cp_async16(uint32_t dst, const void* src) {
    asm volatile("cp.async.cg.shared.global [%0], [%1], 16;" :: "r"(dst), "l"(src) : "memory");
}
#define CP_COMMIT() asm volatile("cp.async.commit_group;" ::: "memory")
#define CP_WAIT(n)  asm volatile("cp.async.wait_group %0;" :: "n"(n) : "memory")

// D += A * B  (m16n8k8 tf32)
__device__ __forceinline__ void mma_tf32(float* d, const uint32_t* a, const uint32_t* b) {
    asm volatile(
        "mma.sync.aligned.m16n8k8.row.col.f32.tf32.tf32.f32 "
        "{%0,%1,%2,%3}, {%4,%5,%6,%7}, {%8,%9}, {%0,%1,%2,%3};"
        : "+f"(d[0]), "+f"(d[1]), "+f"(d[2]), "+f"(d[3])
        : "r"(a[0]), "r"(a[1]), "r"(a[2]), "r"(a[3]), "r"(b[0]), "r"(b[1]));
}

// ---------------- weight rounding (fp32 -> tf32-rounded fp32) ----------------
__global__ __launch_bounds__(256) void round_tf32_kernel(
    const float4* __restrict__ in, float4* __restrict__ out, int n4)
{
    int i = blockIdx.x * 256 + threadIdx.x;
    if (i < n4) {
        float4 v = in[i];
        v.x = tf32r(v.x); v.y = tf32r(v.y); v.z = tf32r(v.z); v.w = tf32r(v.w);
        out[i] = v;
    }
}

// ---------------- LayerNorm (output tf32-rounded: feeds a GEMM) ----------------
__global__ __launch_bounds__(256) void ln_kernel(
    const float* __restrict__ x, const float* __restrict__ g,
    const float* __restrict__ b, float* __restrict__ out)
{
    int row = blockIdx.x;
    const float* xr = x + (size_t)row * D_EMB;
    float sum = 0.f, sq = 0.f;
    for (int i = threadIdx.x; i < D_EMB; i += 256) {
        float v = xr[i]; sum += v; sq += v * v;
    }
    __shared__ float s1[8], s2[8];
    #pragma unroll
    for (int o = 16; o > 0; o >>= 1) {
        sum += __shfl_down_sync(0xffffffffu, sum, o);
        sq  += __shfl_down_sync(0xffffffffu, sq, o);
    }
    int w = threadIdx.x >> 5, l = threadIdx.x & 31;
    if (l == 0) { s1[w] = sum; s2[w] = sq; }
    __syncthreads();
    if (threadIdx.x == 0) {
        float a = 0.f, c = 0.f;
        #pragma unroll
        for (int i = 0; i < 8; i++) { a += s1[i]; c += s2[i]; }
        s1[0] = a * (1.0f / D_EMB);
        s2[0] = c * (1.0f / D_EMB);
    }
    __syncthreads();
    float mu = s1[0];
    float rstd = rsqrtf(s2[0] - mu * mu + 1e-6f);
    float* orow = out + (size_t)row * D_EMB;
    for (int i = threadIdx.x; i < D_EMB; i += 256)
        orow[i] = tf32r((xr[i] - mu) * rstd * g[i] + b[i]);
}

// ---------------- tf32 mma.sync GEMM: C[M,N] = A[M,K]*B[N,K]^T + epilogue ----
// MODE 0: +bias    MODE 1: +bias+res    MODE 2: gelu(+bias), tf32-rounded out
// 128x128x32 CTA tile, 8 warps (2 x 4), warp tile 64x32.
#define SM_STRIDE 36              // floats per smem row (16B aligned, conflict-free)
#define STAGE_FLTS (128 * SM_STRIDE * 2)   // A tile + B tile per stage
template <int MODE>
__global__ __launch_bounds__(256, 2) void mma_gemm(
    const float* __restrict__ A, const float* __restrict__ B,
    const float* __restrict__ bias, const float* __restrict__ res,
    float* __restrict__ C, int M, int N, int K)
{
    extern __shared__ float sm[];
    const int tid = threadIdx.x, wid = tid >> 5, lane = tid & 31;
    const int g = lane >> 2, t = lane & 3;    // groupID, threadID_in_group
    const int wm = wid >> 2, wn = wid & 3;    // warp coords: 2 x 4
    const int m0 = blockIdx.y * 128, n0 = blockIdx.x * 128;
    const int NC = K >> 5;                    // K-chunks of 32

    const float* Agb = A + (size_t)m0 * K;
    const float* Bgb = B + (size_t)n0 * K;

    float acc[4][4][4];
    #pragma unroll
    for (int i = 0; i < 4; i++)
        #pragma unroll
        for (int j = 0; j < 4; j++)
            #pragma unroll
            for (int q = 0; q < 4; q++) acc[i][j][q] = 0.f;

    // load one 128x32 A tile + 128x32 B tile into stage s
    auto load_tile = [&](int kc, int s) {
        float* a_s = sm + s * STAGE_FLTS;
        float* b_s = a_s + 128 * SM_STRIDE;
        const float* Ap = Agb + kc * 32;
        const float* Bp = Bgb + kc * 32;
        #pragma unroll
        for (int q = 0; q < 4; q++) {
            int it = tid + q * 256;        // 0..1023
            int r = it >> 3, c = it & 7;   // row, 16B-chunk
            cp_async16(s2u(a_s + r * SM_STRIDE + c * 4), Ap + (size_t)r * K + c * 4);
            cp_async16(s2u(b_s + r * SM_STRIDE + c * 4), Bp + (size_t)r * K + c * 4);
        }
        CP_COMMIT();
    };

    load_tile(0, 0);

    for (int c = 0; c < NC; c++) {
        int cur = c & 1;
        if (c + 1 < NC) { load_tile(c + 1, cur ^ 1); CP_WAIT(1); }
        else            { CP_WAIT(0); }
        __syncthreads();

        const float* a_s = sm + cur * STAGE_FLTS + (wm * 64) * SM_STRIDE;
        const float* b_s = sm + cur * STAGE_FLTS + 128 * SM_STRIDE + (wn * 32) * SM_STRIDE;

        #pragma unroll
        for (int ks = 0; ks < 4; ks++) {
            const int kb = ks * 8;
            uint32_t afr[4][4];
            #pragma unroll
            for (int i = 0; i < 4; i++) {
                const float* ap = a_s + (i * 16 + g) * SM_STRIDE + kb + t;
                afr[i][0] = __float_as_uint(ap[0]);
                afr[i][1] = __float_as_uint(ap[8 * SM_STRIDE]);
                afr[i][2] = __float_as_uint(ap[4]);
                afr[i][3] = __float_as_uint(ap[8 * SM_STRIDE + 4]);
            }
            uint32_t bfr[4][2];
            #pragma unroll
            for (int j = 0; j < 4; j++) {
                const float* bp = b_s + (j * 8 + g) * SM_STRIDE + kb + t;
                bfr[j][0] = __float_as_uint(bp[0]);
                bfr[j][1] = __float_as_uint(bp[4]);
            }
            #pragma unroll
            for (int i = 0; i < 4; i++)
                #pragma unroll
                for (int j = 0; j < 4; j++)
                    mma_tf32(acc[i][j], afr[i], bfr[j]);
        }
        __syncthreads();
    }

    // epilogue
    #pragma unroll
    for (int i = 0; i < 4; i++) {
        const int r0 = m0 + wm * 64 + i * 16 + g;
        #pragma unroll
        for (int j = 0; j < 4; j++) {
            const int cc = n0 + wn * 32 + j * 8 + 2 * t;
            float2 bv = *(const float2*)(bias + cc);
            float v00 = acc[i][j][0] + bv.x, v01 = acc[i][j][1] + bv.y;
            float v10 = acc[i][j][2] + bv.x, v11 = acc[i][j][3] + bv.y;
            if (MODE == 1) {
                float2 r0v = *(const float2*)(res + (size_t)r0 * N + cc);
                float2 r1v = *(const float2*)(res + (size_t)(r0 + 8) * N + cc);
                v00 += r0v.x; v01 += r0v.y; v10 += r1v.x; v11 += r1v.y;
            }
            if (MODE == 2) {
                v00 = tf32r(0.5f * v00 * (1.0f + erff(v00 * 0.70710678118654752f)));
                v01 = tf32r(0.5f * v01 * (1.0f + erff(v01 * 0.70710678118654752f)));
                v10 = tf32r(0.5f * v10 * (1.0f + erff(v10 * 0.70710678118654752f)));
                v11 = tf32r(0.5f * v11 * (1.0f + erff(v11 * 0.70710678118654752f)));
            }
            *(float2*)(C + (size_t)r0 * N + cc)       = make_float2(v00, v01);
            *(float2*)(C + (size_t)(r0 + 8) * N + cc) = make_float2(v10, v11);
        }
    }
}

// ---------------- Flash attention: 64-query tile per block ----------------
#define LDP 65
__global__ __launch_bounds__(256) void attn_kernel(
    const float* __restrict__ qkv, float* __restrict__ ctx)
{
    extern __shared__ float sma[];
    float* Qs = sma;
    float* Ks = Qs + 64 * LDP;
    float* Vs = Ks + 64 * LDP;
    float* Ss = Vs + 64 * LDP;      // transposed S[c][r]
    float* row_m = Ss + 64 * LDP;
    float* row_l = row_m + 64;
    float* row_a = row_l + 64;

    int tid = threadIdx.x;
    int bh = blockIdx.y;
    int b = bh / N_HEAD, h = bh % N_HEAD;
    int q0 = blockIdx.x * 64;
    size_t tok_base = (size_t)b * N_SEQ;
    int hoff = h * HD;

    for (int it = tid; it < 64 * 16; it += 256) {
        int r = it >> 4, c4 = (it & 15) * 4;
        size_t tk = tok_base + q0 + r;
        float4 q = *(const float4*)(qkv + tk * 2304 + hoff + c4);
        float* qr = Qs + r * LDP + c4;
        qr[0] = q.x; qr[1] = q.y; qr[2] = q.z; qr[3] = q.w;
    }
    if (tid < 64) { row_m[tid] = -1e30f; row_l[tid] = 0.f; }

    int ty = tid >> 4, tx = tid & 15;
    float o[4][4];
    #pragma unroll
    for (int i = 0; i < 4; i++)
        #pragma unroll
        for (int j = 0; j < 4; j++) o[i][j] = 0.f;
    const float scale = 0.125f;
    __syncthreads();

    for (int kt = 0; kt < N_SEQ / 64; kt++) {
        for (int it = tid; it < 64 * 16; it += 256) {
            int r = it >> 4, c4 = (it & 15) * 4;
            size_t tk = tok_base + kt * 64 + r;
            float4 kk4 = *(const float4*)(qkv + tk * 2304 + D_EMB + hoff + c4);
            float4 vv4 = *(const float4*)(qkv + tk * 2304 + 2 * D_EMB + hoff + c4);
            float* kr = Ks + r * LDP + c4;
            float* vr = Vs + r * LDP + c4;
            kr[0] = kk4.x; kr[1] = kk4.y; kr[2] = kk4.z; kr[3] = kk4.w;
            vr[0] = vv4.x; vr[1] = vv4.y; vr[2] = vv4.z; vr[3] = vv4.w;
        }
        __syncthreads();

        float s[4][4];
        #pragma unroll
        for (int i = 0; i < 4; i++)
            #pragma unroll
            for (int j = 0; j < 4; j++) s[i][j] = 0.f;
        #pragma unroll 8
        for (int d = 0; d < 64; d++) {
            float qa[4], kb[4];
            #pragma unroll
            for (int i = 0; i < 4; i++) qa[i] = Qs[(ty * 4 + i) * LDP + d];
            #pragma unroll
            for (int j = 0; j < 4; j++) kb[j] = Ks[(tx * 4 + j) * LDP + d];
            #pragma unroll
            for (int i = 0; i < 4; i++)
                #pragma unroll
                for (int j = 0; j < 4; j++) s[i][j] += qa[i] * kb[j];
        }
        #pragma unroll
        for (int i = 0; i < 4; i++)
            #pragma unroll
            for (int j = 0; j < 4; j++)
                Ss[(tx * 4 + j) * LDP + ty * 4 + i] = s[i][j] * scale;
        __syncthreads();

        if (tid < 64) {
            int r = tid;
            float m = row_m[r];
            #pragma unroll 8
            for (int c = 0; c < 64; c++) m = fmaxf(m, Ss[c * LDP + r]);
            float l = 0.f;
            #pragma unroll 8
            for (int c = 0; c < 64; c++) {
                float p = __expf(Ss[c * LDP + r] - m);
                Ss[c * LDP + r] = p;
                l += p;
            }
            float alpha = __expf(row_m[r] - m);
            row_a[r] = alpha;
            row_l[r] = row_l[r] * alpha + l;
            row_m[r] = m;
        }
        __syncthreads();

        float al[4];
        #pragma unroll
        for (int i = 0; i < 4; i++) al[i] = row_a[ty * 4 + i];
        #pragma unroll
        for (int i = 0; i < 4; i++)
            #pragma unroll
            for (int j = 0; j < 4; j++) o[i][j] *= al[i];
        #pragma unroll 8
        for (int kk = 0; kk < 64; kk++) {
            float p[4], v[4];
            #pragma unroll
            for (int i = 0; i < 4; i++) p[i] = Ss[kk * LDP + ty * 4 + i];
            #pragma unroll
            for (int j = 0; j < 4; j++) v[j] = Vs[kk * LDP + tx * 4 + j];
            #pragma unroll
            for (int i = 0; i < 4; i++)
                #pragma unroll
                for (int j = 0; j < 4; j++) o[i][j] += p[i] * v[j];
        }
        __syncthreads();
    }

    #pragma unroll
    for (int i = 0; i < 4; i++) {
        int r = ty * 4 + i;
        float inv = 1.0f / row_l[r];
        size_t tk = tok_base + q0 + r;
        float* orow = ctx + tk * D_EMB + hoff + tx * 4;
        #pragma unroll
        for (int j = 0; j < 4; j++) orow[j] = tf32r(o[i][j] * inv);  // feeds proj GEMM
    }
}

// ---------------- host launcher ----------------
extern "C" void kernel_launch(void* const* d_in, const int* in_sizes, int n_in,
                              void* d_out, int out_size)
{
    const float* x      = (const float*)d_in[0];
    const float* ln1_g  = (const float*)d_in[1];
    const float* ln1_b  = (const float*)d_in[2];
    const float* qkv_w  = (const float*)d_in[3];
    const float* qkv_b  = (const float*)d_in[4];
    const float* proj_w = (const float*)d_in[5];
    const float* proj_b = (const float*)d_in[6];
    const float* ln2_g  = (const float*)d_in[7];
    const float* ln2_b  = (const float*)d_in[8];
    const float* fc1_w  = (const float*)d_in[9];
    const float* fc1_b  = (const float*)d_in[10];
    const float* fc2_w  = (const float*)d_in[11];
    const float* fc2_b  = (const float*)d_in[12];
    float* out = (float*)d_out;

    float *p_xn, *p_qkv, *p_ctx, *p_x1, *p_h, *p_wq, *p_wp, *p_w1, *p_w2;
    cudaGetSymbolAddress((void**)&p_xn,  g_xn);
    cudaGetSymbolAddress((void**)&p_qkv, g_qkv);
    cudaGetSymbolAddress((void**)&p_ctx, g_ctx);
    cudaGetSymbolAddress((void**)&p_x1,  g_x1);
    cudaGetSymbolAddress((void**)&p_h,   g_h);
    cudaGetSymbolAddress((void**)&p_wq,  g_wq);
    cudaGetSymbolAddress((void**)&p_wp,  g_wp);
    cudaGetSymbolAddress((void**)&p_w1,  g_w1);
    cudaGetSymbolAddress((void**)&p_w2,  g_w2);

    const int attn_smem = (4 * 64 * LDP + 3 * 64) * (int)sizeof(float);
    cudaFuncSetAttribute(attn_kernel, cudaFuncAttributeMaxDynamicSharedMemorySize, attn_smem);
    const int gemm_smem = 2 * STAGE_FLTS * (int)sizeof(float);   // 73728 B
    cudaFuncSetAttribute(mma_gemm<0>, cudaFuncAttributeMaxDynamicSharedMemorySize, gemm_smem);
    cudaFuncSetAttribute(mma_gemm<1>, cudaFuncAttributeMaxDynamicSharedMemorySize, gemm_smem);
    cudaFuncSetAttribute(mma_gemm<2>, cudaFuncAttributeMaxDynamicSharedMemorySize, gemm_smem);

    // 0. round weights to tf32 grid (unbiased rna rounding)
    {
        int n;
        n = 3 * D_EMB * D_EMB / 4;
        round_tf32_kernel<<<(n + 255) / 256, 256>>>((const float4*)qkv_w,  (float4*)p_wq, n);
        n = D_EMB * D_EMB / 4;
        round_tf32_kernel<<<(n + 255) / 256, 256>>>((const float4*)proj_w, (float4*)p_wp, n);
        n = D_HID * D_EMB / 4;
        round_tf32_kernel<<<(n + 255) / 256, 256>>>((const float4*)fc1_w,  (float4*)p_w1, n);
        n = D_EMB * D_HID / 4;
        round_tf32_kernel<<<(n + 255) / 256, 256>>>((const float4*)fc2_w,  (float4*)p_w2, n);
    }

    // 1. LN1 (tf32-rounded output)
    ln_kernel<<<T_TOK, 256>>>(x, ln1_g, ln1_b, p_xn);
    // 2. QKV = xn @ qkv_w^T + b
    mma_gemm<0><<<dim3(2304 / 128, T_TOK / 128), 256, gemm_smem>>>(
        p_xn, p_wq, qkv_b, nullptr, p_qkv, T_TOK, 2304, D_EMB);
    // 3. flash attention (ctx tf32-rounded)
    attn_kernel<<<dim3(N_SEQ / 64, N_BATCH * N_HEAD), 256, attn_smem>>>(p_qkv, p_ctx);
    // 4. x1 = x + ctx @ proj_w^T + proj_b
    mma_gemm<1><<<dim3(D_EMB / 128, T_TOK / 128), 256, gemm_smem>>>(
        p_ctx, p_wp, proj_b, x, p_x1, T_TOK, D_EMB, D_EMB);
    // 5. LN2 (tf32-rounded output)
    ln_kernel<<<T_TOK, 256>>>(p_x1, ln2_g, ln2_b, p_xn);
    // 6. h = gelu(xn @ fc1_w^T + fc1_b), tf32-rounded
    mma_gemm<2><<<dim3(D_HID / 128, T_TOK / 128), 256, gemm_smem>>>(
        p_xn, p_w1, fc1_b, nullptr, p_h, T_TOK, D_HID, D_EMB);
    // 7. out = x1 + h @ fc2_w^T + fc2_b
    mma_gemm<1><<<dim3(D_EMB / 128, T_TOK / 128), 256, gemm_smem>>>(
        p_h, p_w2, fc2_b, p_x1, out, T_TOK, D_EMB, D_HID);
}

// round 4
// speedup vs baseline: 2.7466x; 1.2684x over previous
#include <cuda_runtime.h>
#include <cuda_fp16.h>
#include <math.h>
#include <stdint.h>

#define T_TOK   16384
#define D_EMB   768
#define D_HID   3072
#define N_HEAD  12
#define HD      64
#define N_SEQ   1024
#define N_BATCH 16

// ---------------- scratch (device globals: allocation-free) ----------------
__device__ __half g_xn [T_TOK * D_EMB];
__device__ __half g_qkv[T_TOK * 3 * D_EMB];
__device__ __half g_ctx[T_TOK * D_EMB];
__device__ float  g_x1 [T_TOK * D_EMB];
__device__ __half g_h  [T_TOK * D_HID];
// fp16 weights
__device__ __half g_wq[3 * D_EMB * D_EMB];
__device__ __half g_wp[D_EMB * D_EMB];
__device__ __half g_w1[D_HID * D_EMB];
__device__ __half g_w2[D_EMB * D_HID];

// ---------------- helpers ----------------
__device__ __forceinline__ uint32_t s2u(const void* p) {
    uint32_t a;
    asm("{ .reg .u64 t; cvta.to.shared.u64 t, %1; cvt.u32.u64 %0, t; }" : "=r"(a) : "l"(p));
    return a;
}
__device__ __forceinline__ void cp_async16(uint32_t dst, const void* src) {
    asm volatile("cp.async.cg.shared.global [%0], [%1], 16;" :: "r"(dst), "l"(src) : "memory");
}
#define CP_COMMIT() asm volatile("cp.async.commit_group;" ::: "memory")
#define CP_WAIT(n)  asm volatile("cp.async.wait_group %0;" :: "n"(n) : "memory")

__device__ __forceinline__ uint32_t lds32(uint32_t addr) {
    uint32_t v;
    asm volatile("ld.shared.b32 %0, [%1];" : "=r"(v) : "r"(addr));
    return v;
}

// D += A * B  (m16n8k16 fp16, fp32 accum)
__device__ __forceinline__ void mma_f16(float* d, const uint32_t* a, const uint32_t* b) {
    asm volatile(
        "mma.sync.aligned.m16n8k16.row.col.f32.f16.f16.f32 "
        "{%0,%1,%2,%3}, {%4,%5,%6,%7}, {%8,%9}, {%0,%1,%2,%3};"
        : "+f"(d[0]), "+f"(d[1]), "+f"(d[2]), "+f"(d[3])
        : "r"(a[0]), "r"(a[1]), "r"(a[2]), "r"(a[3]), "r"(b[0]), "r"(b[1]));
}

// ---------------- weight conversion fp32 -> fp16 ----------------
__global__ __launch_bounds__(256) void round_h_kernel(
    const float4* __restrict__ in, __half2* __restrict__ out, int n4)
{
    int i = blockIdx.x * 256 + threadIdx.x;
    if (i < n4) {
        float4 v = in[i];
        out[2 * i]     = __floats2half2_rn(v.x, v.y);
        out[2 * i + 1] = __floats2half2_rn(v.z, v.w);
    }
}

// ---------------- LayerNorm (fp32 in, fp16 out: feeds a GEMM) ----------------
__global__ __launch_bounds__(256) void ln_kernel(
    const float* __restrict__ x, const float* __restrict__ g,
    const float* __restrict__ b, __half* __restrict__ out)
{
    int row = blockIdx.x;
    const float* xr = x + (size_t)row * D_EMB;
    float sum = 0.f, sq = 0.f;
    for (int i = threadIdx.x; i < D_EMB; i += 256) {
        float v = xr[i]; sum += v; sq += v * v;
    }
    __shared__ float s1[8], s2[8];
    #pragma unroll
    for (int o = 16; o > 0; o >>= 1) {
        sum += __shfl_down_sync(0xffffffffu, sum, o);
        sq  += __shfl_down_sync(0xffffffffu, sq, o);
    }
    int w = threadIdx.x >> 5, l = threadIdx.x & 31;
    if (l == 0) { s1[w] = sum; s2[w] = sq; }
    __syncthreads();
    if (threadIdx.x == 0) {
        float a = 0.f, c = 0.f;
        #pragma unroll
        for (int i = 0; i < 8; i++) { a += s1[i]; c += s2[i]; }
        s1[0] = a * (1.0f / D_EMB);
        s2[0] = c * (1.0f / D_EMB);
    }
    __syncthreads();
    float mu = s1[0];
    float rstd = rsqrtf(s2[0] - mu * mu + 1e-6f);
    __half* orow = out + (size_t)row * D_EMB;
    for (int i = threadIdx.x; i < D_EMB; i += 256)
        orow[i] = __float2half_rn((xr[i] - mu) * rstd * g[i] + b[i]);
}

// ---------------- fp16 mma GEMM: C[M,N] = A[M,K]*B[N,K]^T + epilogue ----
// MODE 0: +bias -> half   MODE 1: +bias+res -> float   MODE 2: gelu(+bias) -> half
// 128x128x32 CTA tile, 8 warps (2 x 4), warp tile 64x32, 3-stage cp.async.
// smem tile layout: 128 rows x 32 halfs; row = 4 x 16B chunks, chunk col swizzled
// with c' = c ^ ((row>>1)&3)  (conflict-free for both cp.async stores and LDS.32).
#define TILE_BYTES  8192u            // 128 * 64 B
#define STAGE_BYTES 16384u           // A + B
#define STAGES 3
template <int MODE>
__global__ __launch_bounds__(256, 2) void mma_gemm_h(
    const __half* __restrict__ A, const __half* __restrict__ B,
    const float* __restrict__ bias, const float* __restrict__ res,
    void* __restrict__ Cout, int M, int N, int K)
{
    extern __shared__ char smc[];
    const uint32_t sbase = s2u(smc);
    const int tid = threadIdx.x, wid = tid >> 5, lane = tid & 31;
    const int g = lane >> 2, t = lane & 3;
    const int wm = wid >> 2, wn = wid & 3;   // 2 x 4 warps
    const int m0 = blockIdx.y * 128, n0 = blockIdx.x * 128;
    const int NC = K >> 5;

    const __half* Agb = A + (size_t)m0 * K;
    const __half* Bgb = B + (size_t)n0 * K;

    float acc[4][4][4];
    #pragma unroll
    for (int i = 0; i < 4; i++)
        #pragma unroll
        for (int j = 0; j < 4; j++)
            #pragma unroll
            for (int q = 0; q < 4; q++) acc[i][j][q] = 0.f;

    // fragment row offsets (bytes, relative to tile base), + t*4 within chunk
    uint32_t arel[4][2], brel[4];
    #pragma unroll
    for (int i = 0; i < 4; i++) {
        int r = wm * 64 + i * 16 + g;
        arel[i][0] = (uint32_t)(r * 64 + t * 4);
        arel[i][1] = (uint32_t)((r + 8) * 64 + t * 4);
    }
    #pragma unroll
    for (int j = 0; j < 4; j++) {
        int r = wn * 32 + j * 8 + g;
        brel[j] = (uint32_t)(r * 64 + t * 4);
    }
    // chunk-offset table: all fragment rows share xor value (g>>1)&3
    const uint32_t xg = (uint32_t)((lane >> 3) & 3);
    uint32_t co[4];
    #pragma unroll
    for (int u = 0; u < 4; u++) co[u] = ((uint32_t)u ^ xg) << 4;

    auto load_tile = [&](int kc, int s) {
        uint32_t sa = sbase + (uint32_t)s * STAGE_BYTES;
        uint32_t sb = sa + TILE_BYTES;
        const __half* Ap = Agb + (size_t)kc * 32;
        const __half* Bp = Bgb + (size_t)kc * 32;
        #pragma unroll
        for (int q = 0; q < 2; q++) {
            int it = tid + q * 256;          // 0..511
            int r = it >> 2, c = it & 3;
            uint32_t ci = (uint32_t)(r * 4) + ((uint32_t)c ^ (uint32_t)((r >> 1) & 3));
            cp_async16(sa + ci * 16u, Ap + (size_t)r * K + c * 8);
            cp_async16(sb + ci * 16u, Bp + (size_t)r * K + c * 8);
        }
        CP_COMMIT();
    };

    load_tile(0, 0);
    load_tile(1, 1);

    for (int c = 0; c < NC; c++) {
        int cur = c % STAGES;
        if (c + 2 < NC) { load_tile(c + 2, (c + 2) % STAGES); CP_WAIT(2); }
        else if (c + 1 < NC) { CP_WAIT(1); }
        else { CP_WAIT(0); }
        __syncthreads();

        const uint32_t ab = sbase + (uint32_t)cur * STAGE_BYTES;
        const uint32_t bb = ab + TILE_BYTES;

        #pragma unroll
        for (int ks = 0; ks < 2; ks++) {
            const uint32_t c0 = co[2 * ks], c1 = co[2 * ks + 1];
            uint32_t afr[4][4];
            #pragma unroll
            for (int i = 0; i < 4; i++) {
                afr[i][0] = lds32(ab + arel[i][0] + c0);
                afr[i][1] = lds32(ab + arel[i][1] + c0);
                afr[i][2] = lds32(ab + arel[i][0] + c1);
                afr[i][3] = lds32(ab + arel[i][1] + c1);
            }
            uint32_t bfr[4][2];
            #pragma unroll
            for (int j = 0; j < 4; j++) {
                bfr[j][0] = lds32(bb + brel[j] + c0);
                bfr[j][1] = lds32(bb + brel[j] + c1);
            }
            #pragma unroll
            for (int i = 0; i < 4; i++)
                #pragma unroll
                for (int j = 0; j < 4; j++)
                    mma_f16(acc[i][j], afr[i], bfr[j]);
        }
        __syncthreads();
    }

    // epilogue
    #pragma unroll
    for (int i = 0; i < 4; i++) {
        const int r0 = m0 + wm * 64 + i * 16 + g;
        #pragma unroll
        for (int j = 0; j < 4; j++) {
            const int cc = n0 + wn * 32 + j * 8 + 2 * t;
            float2 bv = *(const float2*)(bias + cc);
            float v00 = acc[i][j][0] + bv.x, v01 = acc[i][j][1] + bv.y;
            float v10 = acc[i][j][2] + bv.x, v11 = acc[i][j][3] + bv.y;
            if (MODE == 1) {
                float2 r0v = *(const float2*)(res + (size_t)r0 * N + cc);
                float2 r1v = *(const float2*)(res + (size_t)(r0 + 8) * N + cc);
                v00 += r0v.x; v01 += r0v.y; v10 += r1v.x; v11 += r1v.y;
            }
            if (MODE == 2) {
                v00 = 0.5f * v00 * (1.0f + erff(v00 * 0.70710678118654752f));
                v01 = 0.5f * v01 * (1.0f + erff(v01 * 0.70710678118654752f));
                v10 = 0.5f * v10 * (1.0f + erff(v10 * 0.70710678118654752f));
                v11 = 0.5f * v11 * (1.0f + erff(v11 * 0.70710678118654752f));
            }
            if (MODE == 1) {
                float* Cf = (float*)Cout;
                *(float2*)(Cf + (size_t)r0 * N + cc)       = make_float2(v00, v01);
                *(float2*)(Cf + (size_t)(r0 + 8) * N + cc) = make_float2(v10, v11);
            } else {
                __half* Ch = (__half*)Cout;
                *(__half2*)(Ch + (size_t)r0 * N + cc)       = __floats2half2_rn(v00, v01);
                *(__half2*)(Ch + (size_t)(r0 + 8) * N + cc) = __floats2half2_rn(v10, v11);
            }
        }
    }
}

// ---------------- Flash attention: 64-query tile per block (half qkv in) ----
#define LDP 65
__global__ __launch_bounds__(256) void attn_kernel(
    const __half* __restrict__ qkv, __half* __restrict__ ctx)
{
    extern __shared__ float sma[];
    float* Qs = sma;
    float* Ks = Qs + 64 * LDP;
    float* Vs = Ks + 64 * LDP;
    float* Ss = Vs + 64 * LDP;      // transposed S[c][r]
    float* row_m = Ss + 64 * LDP;
    float* row_l = row_m + 64;
    float* row_a = row_l + 64;

    int tid = threadIdx.x;
    int bh = blockIdx.y;
    int b = bh / N_HEAD, h = bh % N_HEAD;
    int q0 = blockIdx.x * 64;
    size_t tok_base = (size_t)b * N_SEQ;
    int hoff = h * HD;

    // load Q tile (8 halfs per iter)
    for (int it = tid; it < 64 * 8; it += 256) {
        int r = it >> 3, c8 = (it & 7) * 8;
        size_t tk = tok_base + q0 + r;
        const __half2* src = (const __half2*)(qkv + tk * 2304 + hoff + c8);
        float* qr = Qs + r * LDP + c8;
        #pragma unroll
        for (int u = 0; u < 4; u++) {
            float2 f = __half22float2(src[u]);
            qr[2 * u] = f.x; qr[2 * u + 1] = f.y;
        }
    }
    if (tid < 64) { row_m[tid] = -1e30f; row_l[tid] = 0.f; }

    int ty = tid >> 4, tx = tid & 15;
    float o[4][4];
    #pragma unroll
    for (int i = 0; i < 4; i++)
        #pragma unroll
        for (int j = 0; j < 4; j++) o[i][j] = 0.f;
    const float scale = 0.125f;
    __syncthreads();

    for (int kt = 0; kt < N_SEQ / 64; kt++) {
        for (int it = tid; it < 64 * 8; it += 256) {
            int r = it >> 3, c8 = (it & 7) * 8;
            size_t tk = tok_base + kt * 64 + r;
            const __half2* ks = (const __half2*)(qkv + tk * 2304 + D_EMB + hoff + c8);
            const __half2* vs = (const __half2*)(qkv + tk * 2304 + 2 * D_EMB + hoff + c8);
            float* kr = Ks + r * LDP + c8;
            float* vr = Vs + r * LDP + c8;
            #pragma unroll
            for (int u = 0; u < 4; u++) {
                float2 fk = __half22float2(ks[u]);
                float2 fv = __half22float2(vs[u]);
                kr[2 * u] = fk.x; kr[2 * u + 1] = fk.y;
                vr[2 * u] = fv.x; vr[2 * u + 1] = fv.y;
            }
        }
        __syncthreads();

        float s[4][4];
        #pragma unroll
        for (int i = 0; i < 4; i++)
            #pragma unroll
            for (int j = 0; j < 4; j++) s[i][j] = 0.f;
        #pragma unroll 8
        for (int d = 0; d < 64; d++) {
            float qa[4], kb[4];
            #pragma unroll
            for (int i = 0; i < 4; i++) qa[i] = Qs[(ty * 4 + i) * LDP + d];
            #pragma unroll
            for (int j = 0; j < 4; j++) kb[j] = Ks[(tx * 4 + j) * LDP + d];
            #pragma unroll
            for (int i = 0; i < 4; i++)
                #pragma unroll
                for (int j = 0; j < 4; j++) s[i][j] += qa[i] * kb[j];
        }
        #pragma unroll
        for (int i = 0; i < 4; i++)
            #pragma unroll
            for (int j = 0; j < 4; j++)
                Ss[(tx * 4 + j) * LDP + ty * 4 + i] = s[i][j] * scale;
        __syncthreads();

        if (tid < 64) {
            int r = tid;
            float m = row_m[r];
            #pragma unroll 8
            for (int c = 0; c < 64; c++) m = fmaxf(m, Ss[c * LDP + r]);
            float l = 0.f;
            #pragma unroll 8
            for (int c = 0; c < 64; c++) {
                float p = __expf(Ss[c * LDP + r] - m);
                Ss[c * LDP + r] = p;
                l += p;
            }
            float alpha = __expf(row_m[r] - m);
            row_a[r] = alpha;
            row_l[r] = row_l[r] * alpha + l;
            row_m[r] = m;
        }
        __syncthreads();

        float al[4];
        #pragma unroll
        for (int i = 0; i < 4; i++) al[i] = row_a[ty * 4 + i];
        #pragma unroll
        for (int i = 0; i < 4; i++)
            #pragma unroll
            for (int j = 0; j < 4; j++) o[i][j] *= al[i];
        #pragma unroll 8
        for (int kk = 0; kk < 64; kk++) {
            float p[4], v[4];
            #pragma unroll
            for (int i = 0; i < 4; i++) p[i] = Ss[kk * LDP + ty * 4 + i];
            #pragma unroll
            for (int j = 0; j < 4; j++) v[j] = Vs[kk * LDP + tx * 4 + j];
            #pragma unroll
            for (int i = 0; i < 4; i++)
                #pragma unroll
                for (int j = 0; j < 4; j++) o[i][j] += p[i] * v[j];
        }
        __syncthreads();
    }

    #pragma unroll
    for (int i = 0; i < 4; i++) {
        int r = ty * 4 + i;
        float inv = 1.0f / row_l[r];
        size_t tk = tok_base + q0 + r;
        __half2* op = (__half2*)(ctx + tk * D_EMB + hoff + tx * 4);
        op[0] = __floats2half2_rn(o[i][0] * inv, o[i][1] * inv);
        op[1] = __floats2half2_rn(o[i][2] * inv, o[i][3] * inv);
    }
}

// ---------------- host launcher ----------------
extern "C" void kernel_launch(void* const* d_in, const int* in_sizes, int n_in,
                              void* d_out, int out_size)
{
    const float* x      = (const float*)d_in[0];
    const float* ln1_g  = (const float*)d_in[1];
    const float* ln1_b  = (const float*)d_in[2];
    const float* qkv_w  = (const float*)d_in[3];
    const float* qkv_b  = (const float*)d_in[4];
    const float* proj_w = (const float*)d_in[5];
    const float* proj_b = (const float*)d_in[6];
    const float* ln2_g  = (const float*)d_in[7];
    const float* ln2_b  = (const float*)d_in[8];
    const float* fc1_w  = (const float*)d_in[9];
    const float* fc1_b  = (const float*)d_in[10];
    const float* fc2_w  = (const float*)d_in[11];
    const float* fc2_b  = (const float*)d_in[12];
    float* out = (float*)d_out;

    __half *p_xn, *p_qkv, *p_ctx, *p_h, *p_wq, *p_wp, *p_w1, *p_w2;
    float *p_x1;
    cudaGetSymbolAddress((void**)&p_xn,  g_xn);
    cudaGetSymbolAddress((void**)&p_qkv, g_qkv);
    cudaGetSymbolAddress((void**)&p_ctx, g_ctx);
    cudaGetSymbolAddress((void**)&p_x1,  g_x1);
    cudaGetSymbolAddress((void**)&p_h,   g_h);
    cudaGetSymbolAddress((void**)&p_wq,  g_wq);
    cudaGetSymbolAddress((void**)&p_wp,  g_wp);
    cudaGetSymbolAddress((void**)&p_w1,  g_w1);
    cudaGetSymbolAddress((void**)&p_w2,  g_w2);

    const int attn_smem = (4 * 64 * LDP + 3 * 64) * (int)sizeof(float);
    cudaFuncSetAttribute(attn_kernel, cudaFuncAttributeMaxDynamicSharedMemorySize, attn_smem);
    const int gemm_smem = STAGES * (int)STAGE_BYTES;   // 49152 B
    cudaFuncSetAttribute(mma_gemm_h<0>, cudaFuncAttributeMaxDynamicSharedMemorySize, gemm_smem);
    cudaFuncSetAttribute(mma_gemm_h<1>, cudaFuncAttributeMaxDynamicSharedMemorySize, gemm_smem);
    cudaFuncSetAttribute(mma_gemm_h<2>, cudaFuncAttributeMaxDynamicSharedMemorySize, gemm_smem);

    // 0. convert weights to fp16
    {
        int n;
        n = 3 * D_EMB * D_EMB / 4;
        round_h_kernel<<<(n + 255) / 256, 256>>>((const float4*)qkv_w,  (__half2*)p_wq, n);
        n = D_EMB * D_EMB / 4;
        round_h_kernel<<<(n + 255) / 256, 256>>>((const float4*)proj_w, (__half2*)p_wp, n);
        n = D_HID * D_EMB / 4;
        round_h_kernel<<<(n + 255) / 256, 256>>>((const float4*)fc1_w,  (__half2*)p_w1, n);
        n = D_EMB * D_HID / 4;
        round_h_kernel<<<(n + 255) / 256, 256>>>((const float4*)fc2_w,  (__half2*)p_w2, n);
    }

    // 1. LN1 -> half
    ln_kernel<<<T_TOK, 256>>>(x, ln1_g, ln1_b, p_xn);
    // 2. QKV = xn @ qkv_w^T + b  -> half
    mma_gemm_h<0><<<dim3(2304 / 128, T_TOK / 128), 256, gemm_smem>>>(
        p_xn, p_wq, qkv_b, nullptr, p_qkv, T_TOK, 2304, D_EMB);
    // 3. flash attention -> half ctx
    attn_kernel<<<dim3(N_SEQ / 64, N_BATCH * N_HEAD), 256, attn_smem>>>(p_qkv, p_ctx);
    // 4. x1 = x + ctx @ proj_w^T + proj_b  -> fp32
    mma_gemm_h<1><<<dim3(D_EMB / 128, T_TOK / 128), 256, gemm_smem>>>(
        p_ctx, p_wp, proj_b, x, p_x1, T_TOK, D_EMB, D_EMB);
    // 5. LN2 -> half
    ln_kernel<<<T_TOK, 256>>>(p_x1, ln2_g, ln2_b, p_xn);
    // 6. h = gelu(xn @ fc1_w^T + fc1_b) -> half
    mma_gemm_h<2><<<dim3(D_HID / 128, T_TOK / 128), 256, gemm_smem>>>(
        p_xn, p_w1, fc1_b, nullptr, p_h, T_TOK, D_HID, D_EMB);
    // 7. out = x1 + h @ fc2_w^T + fc2_b  -> fp32
    mma_gemm_h<1><<<dim3(D_EMB / 128, T_TOK / 128), 256, gemm_smem>>>(
        p_h, p_w2, fc2_b, p_x1, out, T_TOK, D_EMB, D_HID);
}

// round 5
// speedup vs baseline: 6.0847x; 2.2153x over previous
#include <cuda_runtime.h>
#include <cuda_fp16.h>
#include <math.h>
#include <stdint.h>

#define T_TOK   16384
#define D_EMB   768
#define D_HID   3072
#define N_HEAD  12
#define HD      64
#define N_SEQ   1024
#define N_BATCH 16

// ---------------- scratch (device globals: allocation-free) ----------------
__device__ __half g_xn [T_TOK * D_EMB];
__device__ __half g_qkv[T_TOK * 3 * D_EMB];
__device__ __half g_ctx[T_TOK * D_EMB];
__device__ float  g_x1 [T_TOK * D_EMB];
__device__ __half g_h  [T_TOK * D_HID];
// fp16 weights
__device__ __half g_wq[3 * D_EMB * D_EMB];
__device__ __half g_wp[D_EMB * D_EMB];
__device__ __half g_w1[D_HID * D_EMB];
__device__ __half g_w2[D_EMB * D_HID];

// ---------------- helpers ----------------
__device__ __forceinline__ uint32_t s2u(const void* p) {
    uint32_t a;
    asm("{ .reg .u64 t; cvta.to.shared.u64 t, %1; cvt.u32.u64 %0, t; }" : "=r"(a) : "l"(p));
    return a;
}
__device__ __forceinline__ void cp_async16(uint32_t dst, const void* src) {
    asm volatile("cp.async.cg.shared.global [%0], [%1], 16;" :: "r"(dst), "l"(src) : "memory");
}
#define CP_COMMIT() asm volatile("cp.async.commit_group;" ::: "memory")
#define CP_WAIT(n)  asm volatile("cp.async.wait_group %0;" :: "n"(n) : "memory")

__device__ __forceinline__ uint32_t lds32(uint32_t addr) {
    uint32_t v;
    asm volatile("ld.shared.b32 %0, [%1];" : "=r"(v) : "r"(addr));
    return v;
}
__device__ __forceinline__ void sts32(uint32_t addr, uint32_t v) {
    asm volatile("st.shared.b32 [%0], %1;" :: "r"(addr), "r"(v) : "memory");
}

// D += A * B  (m16n8k16 fp16, fp32 accum)
__device__ __forceinline__ void mma_f16(float* d, const uint32_t* a, const uint32_t* b) {
    asm volatile(
        "mma.sync.aligned.m16n8k16.row.col.f32.f16.f16.f32 "
        "{%0,%1,%2,%3}, {%4,%5,%6,%7}, {%8,%9}, {%0,%1,%2,%3};"
        : "+f"(d[0]), "+f"(d[1]), "+f"(d[2]), "+f"(d[3])
        : "r"(a[0]), "r"(a[1]), "r"(a[2]), "r"(a[3]), "r"(b[0]), "r"(b[1]));
}
__device__ __forceinline__ uint32_t h2u(float a, float b) {
    __half2 h = __floats2half2_rn(a, b);
    return *(uint32_t*)&h;
}

// ---------------- weight conversion fp32 -> fp16 ----------------
__global__ __launch_bounds__(256) void round_h_kernel(
    const float4* __restrict__ in, __half2* __restrict__ out, int n4)
{
    int i = blockIdx.x * 256 + threadIdx.x;
    if (i < n4) {
        float4 v = in[i];
        out[2 * i]     = __floats2half2_rn(v.x, v.y);
        out[2 * i + 1] = __floats2half2_rn(v.z, v.w);
    }
}

// ---------------- LayerNorm (fp32 in, fp16 out) ----------------
__global__ __launch_bounds__(256) void ln_kernel(
    const float* __restrict__ x, const float* __restrict__ g,
    const float* __restrict__ b, __half* __restrict__ out)
{
    int row = blockIdx.x;
    const float* xr = x + (size_t)row * D_EMB;
    float sum = 0.f, sq = 0.f;
    for (int i = threadIdx.x; i < D_EMB; i += 256) {
        float v = xr[i]; sum += v; sq += v * v;
    }
    __shared__ float s1[8], s2[8];
    #pragma unroll
    for (int o = 16; o > 0; o >>= 1) {
        sum += __shfl_down_sync(0xffffffffu, sum, o);
        sq  += __shfl_down_sync(0xffffffffu, sq, o);
    }
    int w = threadIdx.x >> 5, l = threadIdx.x & 31;
    if (l == 0) { s1[w] = sum; s2[w] = sq; }
    __syncthreads();
    if (threadIdx.x == 0) {
        float a = 0.f, c = 0.f;
        #pragma unroll
        for (int i = 0; i < 8; i++) { a += s1[i]; c += s2[i]; }
        s1[0] = a * (1.0f / D_EMB);
        s2[0] = c * (1.0f / D_EMB);
    }
    __syncthreads();
    float mu = s1[0];
    float rstd = rsqrtf(s2[0] - mu * mu + 1e-6f);
    __half* orow = out + (size_t)row * D_EMB;
    for (int i = threadIdx.x; i < D_EMB; i += 256)
        orow[i] = __float2half_rn((xr[i] - mu) * rstd * g[i] + b[i]);
}

// ---------------- fp16 mma GEMM (unchanged from R4) ----------------
#define TILE_BYTES  8192u
#define STAGE_BYTES 16384u
#define STAGES 3
template <int MODE>
__global__ __launch_bounds__(256, 2) void mma_gemm_h(
    const __half* __restrict__ A, const __half* __restrict__ B,
    const float* __restrict__ bias, const float* __restrict__ res,
    void* __restrict__ Cout, int M, int N, int K)
{
    extern __shared__ char smc[];
    const uint32_t sbase = s2u(smc);
    const int tid = threadIdx.x, wid = tid >> 5, lane = tid & 31;
    const int g = lane >> 2, t = lane & 3;
    const int wm = wid >> 2, wn = wid & 3;
    const int m0 = blockIdx.y * 128, n0 = blockIdx.x * 128;
    const int NC = K >> 5;

    const __half* Agb = A + (size_t)m0 * K;
    const __half* Bgb = B + (size_t)n0 * K;

    float acc[4][4][4];
    #pragma unroll
    for (int i = 0; i < 4; i++)
        #pragma unroll
        for (int j = 0; j < 4; j++)
            #pragma unroll
            for (int q = 0; q < 4; q++) acc[i][j][q] = 0.f;

    uint32_t arel[4][2], brel[4];
    #pragma unroll
    for (int i = 0; i < 4; i++) {
        int r = wm * 64 + i * 16 + g;
        arel[i][0] = (uint32_t)(r * 64 + t * 4);
        arel[i][1] = (uint32_t)((r + 8) * 64 + t * 4);
    }
    #pragma unroll
    for (int j = 0; j < 4; j++) {
        int r = wn * 32 + j * 8 + g;
        brel[j] = (uint32_t)(r * 64 + t * 4);
    }
    const uint32_t xg = (uint32_t)((lane >> 3) & 3);
    uint32_t co[4];
    #pragma unroll
    for (int u = 0; u < 4; u++) co[u] = ((uint32_t)u ^ xg) << 4;

    auto load_tile = [&](int kc, int s) {
        uint32_t sa = sbase + (uint32_t)s * STAGE_BYTES;
        uint32_t sb = sa + TILE_BYTES;
        const __half* Ap = Agb + (size_t)kc * 32;
        const __half* Bp = Bgb + (size_t)kc * 32;
        #pragma unroll
        for (int q = 0; q < 2; q++) {
            int it = tid + q * 256;
            int r = it >> 2, c = it & 3;
            uint32_t ci = (uint32_t)(r * 4) + ((uint32_t)c ^ (uint32_t)((r >> 1) & 3));
            cp_async16(sa + ci * 16u, Ap + (size_t)r * K + c * 8);
            cp_async16(sb + ci * 16u, Bp + (size_t)r * K + c * 8);
        }
        CP_COMMIT();
    };

    load_tile(0, 0);
    load_tile(1, 1);

    for (int c = 0; c < NC; c++) {
        int cur = c % STAGES;
        if (c + 2 < NC) { load_tile(c + 2, (c + 2) % STAGES); CP_WAIT(2); }
        else if (c + 1 < NC) { CP_WAIT(1); }
        else { CP_WAIT(0); }
        __syncthreads();

        const uint32_t ab = sbase + (uint32_t)cur * STAGE_BYTES;
        const uint32_t bb = ab + TILE_BYTES;

        #pragma unroll
        for (int ks = 0; ks < 2; ks++) {
            const uint32_t c0 = co[2 * ks], c1 = co[2 * ks + 1];
            uint32_t afr[4][4];
            #pragma unroll
            for (int i = 0; i < 4; i++) {
                afr[i][0] = lds32(ab + arel[i][0] + c0);
                afr[i][1] = lds32(ab + arel[i][1] + c0);
                afr[i][2] = lds32(ab + arel[i][0] + c1);
                afr[i][3] = lds32(ab + arel[i][1] + c1);
            }
            uint32_t bfr[4][2];
            #pragma unroll
            for (int j = 0; j < 4; j++) {
                bfr[j][0] = lds32(bb + brel[j] + c0);
                bfr[j][1] = lds32(bb + brel[j] + c1);
            }
            #pragma unroll
            for (int i = 0; i < 4; i++)
                #pragma unroll
                for (int j = 0; j < 4; j++)
                    mma_f16(acc[i][j], afr[i], bfr[j]);
        }
        __syncthreads();
    }

    #pragma unroll
    for (int i = 0; i < 4; i++) {
        const int r0 = m0 + wm * 64 + i * 16 + g;
        #pragma unroll
        for (int j = 0; j < 4; j++) {
            const int cc = n0 + wn * 32 + j * 8 + 2 * t;
            float2 bv = *(const float2*)(bias + cc);
            float v00 = acc[i][j][0] + bv.x, v01 = acc[i][j][1] + bv.y;
            float v10 = acc[i][j][2] + bv.x, v11 = acc[i][j][3] + bv.y;
            if (MODE == 1) {
                float2 r0v = *(const float2*)(res + (size_t)r0 * N + cc);
                float2 r1v = *(const float2*)(res + (size_t)(r0 + 8) * N + cc);
                v00 += r0v.x; v01 += r0v.y; v10 += r1v.x; v11 += r1v.y;
            }
            if (MODE == 2) {
                v00 = 0.5f * v00 * (1.0f + erff(v00 * 0.70710678118654752f));
                v01 = 0.5f * v01 * (1.0f + erff(v01 * 0.70710678118654752f));
                v10 = 0.5f * v10 * (1.0f + erff(v10 * 0.70710678118654752f));
                v11 = 0.5f * v11 * (1.0f + erff(v11 * 0.70710678118654752f));
            }
            if (MODE == 1) {
                float* Cf = (float*)Cout;
                *(float2*)(Cf + (size_t)r0 * N + cc)       = make_float2(v00, v01);
                *(float2*)(Cf + (size_t)(r0 + 8) * N + cc) = make_float2(v10, v11);
            } else {
                __half* Ch = (__half*)Cout;
                *(__half2*)(Ch + (size_t)r0 * N + cc)       = __floats2half2_rn(v00, v01);
                *(__half2*)(Ch + (size_t)(r0 + 8) * N + cc) = __floats2half2_rn(v10, v11);
            }
        }
    }
}

// ---------------- Flash attention via mma.sync: 128-query tile, 8 warps ----
// warp w owns query rows [w*16, w*16+16): softmax state in registers.
// Q: 128x64 smem (XOR-swizzled 16B chunks), fragments cached in regs.
// K: 64x64 smem double-buffered (cp.async). Vt: transposed 64dim x 72key halfs.
#define VT_STRIDE 72
__global__ __launch_bounds__(256) void attn_mma_kernel(
    const __half* __restrict__ qkv, __half* __restrict__ ctx)
{
    __shared__ __align__(16) char sQ[16384];
    __shared__ __align__(16) char sK[2][8192];
    __shared__ __align__(4)  __half sVt[64 * VT_STRIDE];

    const int tid = threadIdx.x, wid = tid >> 5, lane = tid & 31;
    const int g = lane >> 2, t = lane & 3;
    const int bh = blockIdx.y, b = bh / N_HEAD, h = bh % N_HEAD;
    const int q0 = blockIdx.x * 128;
    const size_t tok_base = (size_t)b * N_SEQ;
    const int hoff = h * HD;
    const uint32_t uQ = s2u(sQ), uVt = s2u(sVt);

    // prologue: Q tile + K block 0
    #pragma unroll
    for (int qi = 0; qi < 4; qi++) {
        int it = tid + qi * 256, r = it >> 3, c = it & 7;
        cp_async16(uQ + (uint32_t)(r * 128 + ((c ^ (r & 7)) * 16)),
                   qkv + (tok_base + q0 + r) * 2304 + hoff + c * 8);
    }
    {
        uint32_t uK0 = s2u(sK[0]);
        #pragma unroll
        for (int qi = 0; qi < 2; qi++) {
            int it = tid + qi * 256, r = it >> 3, c = it & 7;
            cp_async16(uK0 + (uint32_t)(r * 128 + ((c ^ (r & 7)) * 16)),
                       qkv + (tok_base + r) * 2304 + D_EMB + hoff + c * 8);
        }
    }
    CP_COMMIT();
    CP_WAIT(0);
    __syncthreads();

    // Q fragments in registers, pre-scaled by Hd^-0.5 = 0.125
    uint32_t qf[4][4];
    {
        const int rq = wid * 16 + g;
        const __half2 s8 = __floats2half2_rn(0.125f, 0.125f);
        #pragma unroll
        for (int ks = 0; ks < 4; ks++) {
            uint32_t ca = (uint32_t)(((2 * ks) ^ (rq & 7)) * 16 + t * 4);
            uint32_t cb = (uint32_t)(((2 * ks + 1) ^ (rq & 7)) * 16 + t * 4);
            qf[ks][0] = lds32(uQ + rq * 128 + ca);
            qf[ks][1] = lds32(uQ + (rq + 8) * 128 + ca);   // (rq+8)&7 == rq&7
            qf[ks][2] = lds32(uQ + rq * 128 + cb);
            qf[ks][3] = lds32(uQ + (rq + 8) * 128 + cb);
            #pragma unroll
            for (int u = 0; u < 4; u++) {
                __half2 hv = *(__half2*)&qf[ks][u];
                hv = __hmul2(hv, s8);
                qf[ks][u] = *(uint32_t*)&hv;
            }
        }
    }

    float m_g = -1e30f, m_g8 = -1e30f, l_g = 0.f, l_g8 = 0.f;
    float of[8][4];
    #pragma unroll
    for (int j = 0; j < 8; j++)
        #pragma unroll
        for (int q = 0; q < 4; q++) of[j][q] = 0.f;

    const int vq = tid & 31, vd0 = (tid >> 5) * 8;

    for (int kt = 0; kt < N_SEQ / 64; kt++) {
        // V(kt) -> regs (two key rows x 8 dims)
        const float4 v0 = *(const float4*)(qkv + (tok_base + kt * 64 + 2 * vq) * 2304 + 2 * D_EMB + hoff + vd0);
        const float4 v1 = *(const float4*)(qkv + (tok_base + kt * 64 + 2 * vq + 1) * 2304 + 2 * D_EMB + hoff + vd0);

        if (kt > 0) CP_WAIT(0);
        __syncthreads();   // prev PV done reading Vt; K(kt) visible

        // transpose-store V: Vt[d][key], conflict-free (word = d*36 + vq)
        {
            const uint32_t* a0 = (const uint32_t*)&v0;
            const uint32_t* a1 = (const uint32_t*)&v1;
            #pragma unroll
            for (int u2 = 0; u2 < 4; u2++) {
                uint32_t lo = __byte_perm(a0[u2], a1[u2], 0x5410);
                uint32_t hi = __byte_perm(a0[u2], a1[u2], 0x7632);
                sts32(uVt + (uint32_t)((vd0 + 2 * u2) * (VT_STRIDE * 2) + 4 * vq), lo);
                sts32(uVt + (uint32_t)((vd0 + 2 * u2 + 1) * (VT_STRIDE * 2) + 4 * vq), hi);
            }
        }
        // prefetch K(kt+1)
        if (kt + 1 < N_SEQ / 64) {
            uint32_t uKn = s2u(sK[(kt + 1) & 1]);
            #pragma unroll
            for (int qi = 0; qi < 2; qi++) {
                int it = tid + qi * 256, r = it >> 3, c = it & 7;
                cp_async16(uKn + (uint32_t)(r * 128 + ((c ^ (r & 7)) * 16)),
                           qkv + (tok_base + (kt + 1) * 64 + r) * 2304 + D_EMB + hoff + c * 8);
            }
            CP_COMMIT();
        }
        __syncthreads();   // Vt ready

        // S = Q K^T  (8 n-tiles of 8 keys)
        const uint32_t uKb = s2u(sK[kt & 1]);
        float sf[8][4];
        #pragma unroll
        for (int j = 0; j < 8; j++) {
            sf[j][0] = sf[j][1] = sf[j][2] = sf[j][3] = 0.f;
            const int rk = j * 8 + g;
            #pragma unroll
            for (int ks = 0; ks < 4; ks++) {
                uint32_t bb[2];
                bb[0] = lds32(uKb + rk * 128 + (uint32_t)((((2 * ks)     ^ (rk & 7)) * 16) + t * 4));
                bb[1] = lds32(uKb + rk * 128 + (uint32_t)((((2 * ks + 1) ^ (rk & 7)) * 16) + t * 4));
                mma_f16(sf[j], qf[ks], bb);
            }
        }

        // online softmax (rows g and g+8, quad-reduced)
        float mg = m_g, mg8 = m_g8;
        #pragma unroll
        for (int j = 0; j < 8; j++) {
            mg  = fmaxf(mg,  fmaxf(sf[j][0], sf[j][1]));
            mg8 = fmaxf(mg8, fmaxf(sf[j][2], sf[j][3]));
        }
        mg  = fmaxf(mg,  __shfl_xor_sync(0xffffffffu, mg, 1));
        mg  = fmaxf(mg,  __shfl_xor_sync(0xffffffffu, mg, 2));
        mg8 = fmaxf(mg8, __shfl_xor_sync(0xffffffffu, mg8, 1));
        mg8 = fmaxf(mg8, __shfl_xor_sync(0xffffffffu, mg8, 2));
        const float alpha_g = __expf(m_g - mg), alpha_g8 = __expf(m_g8 - mg8);
        m_g = mg; m_g8 = mg8;

        float sl_g = 0.f, sl_g8 = 0.f;
        #pragma unroll
        for (int j = 0; j < 8; j++) {
            sf[j][0] = __expf(sf[j][0] - mg);
            sf[j][1] = __expf(sf[j][1] - mg);
            sf[j][2] = __expf(sf[j][2] - mg8);
            sf[j][3] = __expf(sf[j][3] - mg8);
            sl_g  += sf[j][0] + sf[j][1];
            sl_g8 += sf[j][2] + sf[j][3];
        }
        sl_g  += __shfl_xor_sync(0xffffffffu, sl_g, 1);
        sl_g  += __shfl_xor_sync(0xffffffffu, sl_g, 2);
        sl_g8 += __shfl_xor_sync(0xffffffffu, sl_g8, 1);
        sl_g8 += __shfl_xor_sync(0xffffffffu, sl_g8, 2);
        l_g  = l_g  * alpha_g  + sl_g;
        l_g8 = l_g8 * alpha_g8 + sl_g8;

        // P fragments (C-layout == A-layout pairing)
        uint32_t pf[4][4];
        #pragma unroll
        for (int kp = 0; kp < 4; kp++) {
            pf[kp][0] = h2u(sf[2 * kp][0],     sf[2 * kp][1]);
            pf[kp][1] = h2u(sf[2 * kp][2],     sf[2 * kp][3]);
            pf[kp][2] = h2u(sf[2 * kp + 1][0], sf[2 * kp + 1][1]);
            pf[kp][3] = h2u(sf[2 * kp + 1][2], sf[2 * kp + 1][3]);
        }

        // O = O*alpha + P @ V
        #pragma unroll
        for (int jd = 0; jd < 8; jd++) {
            of[jd][0] *= alpha_g;  of[jd][1] *= alpha_g;
            of[jd][2] *= alpha_g8; of[jd][3] *= alpha_g8;
            const uint32_t vrow = uVt + (uint32_t)((8 * jd + g) * (VT_STRIDE * 2));
            #pragma unroll
            for (int kp = 0; kp < 4; kp++) {
                uint32_t bb[2];
                bb[0] = lds32(vrow + (uint32_t)((16 * kp + 2 * t) * 2));
                bb[1] = lds32(vrow + (uint32_t)((16 * kp + 2 * t + 8) * 2));
                mma_f16(of[jd], pf[kp], bb);
            }
        }
    }

    // epilogue
    const float il_g = 1.0f / l_g, il_g8 = 1.0f / l_g8;
    const int rq = wid * 16 + g;
    #pragma unroll
    for (int jd = 0; jd < 8; jd++) {
        const int col = hoff + 8 * jd + 2 * t;
        *(__half2*)(ctx + (tok_base + q0 + rq) * D_EMB + col) =
            __floats2half2_rn(of[jd][0] * il_g, of[jd][1] * il_g);
        *(__half2*)(ctx + (tok_base + q0 + rq + 8) * D_EMB + col) =
            __floats2half2_rn(of[jd][2] * il_g8, of[jd][3] * il_g8);
    }
}

// ---------------- host launcher ----------------
extern "C" void kernel_launch(void* const* d_in, const int* in_sizes, int n_in,
                              void* d_out, int out_size)
{
    const float* x      = (const float*)d_in[0];
    const float* ln1_g  = (const float*)d_in[1];
    const float* ln1_b  = (const float*)d_in[2];
    const float* qkv_w  = (const float*)d_in[3];
    const float* qkv_b  = (const float*)d_in[4];
    const float* proj_w = (const float*)d_in[5];
    const float* proj_b = (const float*)d_in[6];
    const float* ln2_g  = (const float*)d_in[7];
    const float* ln2_b  = (const float*)d_in[8];
    const float* fc1_w  = (const float*)d_in[9];
    const float* fc1_b  = (const float*)d_in[10];
    const float* fc2_w  = (const float*)d_in[11];
    const float* fc2_b  = (const float*)d_in[12];
    float* out = (float*)d_out;

    __half *p_xn, *p_qkv, *p_ctx, *p_h, *p_wq, *p_wp, *p_w1, *p_w2;
    float *p_x1;
    cudaGetSymbolAddress((void**)&p_xn,  g_xn);
    cudaGetSymbolAddress((void**)&p_qkv, g_qkv);
    cudaGetSymbolAddress((void**)&p_ctx, g_ctx);
    cudaGetSymbolAddress((void**)&p_x1,  g_x1);
    cudaGetSymbolAddress((void**)&p_h,   g_h);
    cudaGetSymbolAddress((void**)&p_wq,  g_wq);
    cudaGetSymbolAddress((void**)&p_wp,  g_wp);
    cudaGetSymbolAddress((void**)&p_w1,  g_w1);
    cudaGetSymbolAddress((void**)&p_w2,  g_w2);

    const int gemm_smem = STAGES * (int)STAGE_BYTES;   // 49152 B
    cudaFuncSetAttribute(mma_gemm_h<0>, cudaFuncAttributeMaxDynamicSharedMemorySize, gemm_smem);
    cudaFuncSetAttribute(mma_gemm_h<1>, cudaFuncAttributeMaxDynamicSharedMemorySize, gemm_smem);
    cudaFuncSetAttribute(mma_gemm_h<2>, cudaFuncAttributeMaxDynamicSharedMemorySize, gemm_smem);

    // 0. convert weights to fp16
    {
        int n;
        n = 3 * D_EMB * D_EMB / 4;
        round_h_kernel<<<(n + 255) / 256, 256>>>((const float4*)qkv_w,  (__half2*)p_wq, n);
        n = D_EMB * D_EMB / 4;
        round_h_kernel<<<(n + 255) / 256, 256>>>((const float4*)proj_w, (__half2*)p_wp, n);
        n = D_HID * D_EMB / 4;
        round_h_kernel<<<(n + 255) / 256, 256>>>((const float4*)fc1_w,  (__half2*)p_w1, n);
        n = D_EMB * D_HID / 4;
        round_h_kernel<<<(n + 255) / 256, 256>>>((const float4*)fc2_w,  (__half2*)p_w2, n);
    }

    // 1. LN1 -> half
    ln_kernel<<<T_TOK, 256>>>(x, ln1_g, ln1_b, p_xn);
    // 2. QKV = xn @ qkv_w^T + b  -> half
    mma_gemm_h<0><<<dim3(2304 / 128, T_TOK / 128), 256, gemm_smem>>>(
        p_xn, p_wq, qkv_b, nullptr, p_qkv, T_TOK, 2304, D_EMB);
    // 3. flash attention (tensor-core) -> half ctx
    attn_mma_kernel<<<dim3(N_SEQ / 128, N_BATCH * N_HEAD), 256>>>(p_qkv, p_ctx);
    // 4. x1 = x + ctx @ proj_w^T + proj_b  -> fp32
    mma_gemm_h<1><<<dim3(D_EMB / 128, T_TOK / 128), 256, gemm_smem>>>(
        p_ctx, p_wp, proj_b, x, p_x1, T_TOK, D_EMB, D_EMB);
    // 5. LN2 -> half
    ln_kernel<<<T_TOK, 256>>>(p_x1, ln2_g, ln2_b, p_xn);
    // 6. h = gelu(xn @ fc1_w^T + fc1_b) -> half
    mma_gemm_h<2><<<dim3(D_HID / 128, T_TOK / 128), 256, gemm_smem>>>(
        p_xn, p_w1, fc1_b, nullptr, p_h, T_TOK, D_HID, D_EMB);
    // 7. out = x1 + h @ fc2_w^T + fc2_b  -> fp32
    mma_gemm_h<1><<<dim3(D_EMB / 128, T_TOK / 128), 256, gemm_smem>>>(
        p_h, p_w2, fc2_b, p_x1, out, T_TOK, D_EMB, D_HID);
}

// round 6
// speedup vs baseline: 7.2324x; 1.1886x over previous
#include <cuda_runtime.h>
#include <cuda_fp16.h>
#include <math.h>
#include <stdint.h>

#define T_TOK   16384
#define D_EMB   768
#define D_HID   3072
#define N_HEAD  12
#define HD      64
#define N_SEQ   1024
#define N_BATCH 16

// ---------------- scratch (device globals: allocation-free) ----------------
__device__ __half g_xn [T_TOK * D_EMB];
__device__ __half g_qkv[T_TOK * 3 * D_EMB];
__device__ __half g_ctx[T_TOK * D_EMB];
__device__ float  g_x1 [T_TOK * D_EMB];
__device__ __half g_h  [T_TOK * D_HID];
__device__ __half g_wq[3 * D_EMB * D_EMB];
__device__ __half g_wp[D_EMB * D_EMB];
__device__ __half g_w1[D_HID * D_EMB];
__device__ __half g_w2[D_EMB * D_HID];

// ---------------- helpers ----------------
__device__ __forceinline__ uint32_t s2u(const void* p) {
    uint32_t a;
    asm("{ .reg .u64 t; cvta.to.shared.u64 t, %1; cvt.u32.u64 %0, t; }" : "=r"(a) : "l"(p));
    return a;
}
__device__ __forceinline__ void cp_async16(uint32_t dst, const void* src) {
    asm volatile("cp.async.cg.shared.global [%0], [%1], 16;" :: "r"(dst), "l"(src) : "memory");
}
#define CP_COMMIT() asm volatile("cp.async.commit_group;" ::: "memory")
#define CP_WAIT(n)  asm volatile("cp.async.wait_group %0;" :: "n"(n) : "memory")

__device__ __forceinline__ uint32_t lds32(uint32_t addr) {
    uint32_t v;
    asm volatile("ld.shared.b32 %0, [%1];" : "=r"(v) : "r"(addr));
    return v;
}
__device__ __forceinline__ void sts32(uint32_t addr, uint32_t v) {
    asm volatile("st.shared.b32 [%0], %1;" :: "r"(addr), "r"(v) : "memory");
}
__device__ __forceinline__ void ldsm_x4(uint32_t* r, uint32_t addr) {
    asm volatile("ldmatrix.sync.aligned.m8n8.x4.shared.b16 {%0,%1,%2,%3}, [%4];"
                 : "=r"(r[0]), "=r"(r[1]), "=r"(r[2]), "=r"(r[3]) : "r"(addr));
}

// D += A * B  (m16n8k16 fp16, fp32 accum)
__device__ __forceinline__ void mma_f16(float* d, const uint32_t* a, const uint32_t* b) {
    asm volatile(
        "mma.sync.aligned.m16n8k16.row.col.f32.f16.f16.f32 "
        "{%0,%1,%2,%3}, {%4,%5,%6,%7}, {%8,%9}, {%0,%1,%2,%3};"
        : "+f"(d[0]), "+f"(d[1]), "+f"(d[2]), "+f"(d[3])
        : "r"(a[0]), "r"(a[1]), "r"(a[2]), "r"(a[3]), "r"(b[0]), "r"(b[1]));
}
__device__ __forceinline__ uint32_t h2u(float a, float b) {
    __half2 h = __floats2half2_rn(a, b);
    return *(uint32_t*)&h;
}

// ---------------- fused weight conversion fp32 -> fp16 (one launch) --------
#define WQ4 442368   // float4 counts per region
#define WP4 147456
#define W14 589824
#define W24 589824
__global__ __launch_bounds__(256) void prep_w_kernel(
    const float4* __restrict__ wq, const float4* __restrict__ wp,
    const float4* __restrict__ w1, const float4* __restrict__ w2,
    __half2* __restrict__ oq, __half2* __restrict__ op,
    __half2* __restrict__ o1, __half2* __restrict__ o2)
{
    int i = blockIdx.x * 256 + threadIdx.x;
    const float4* src; __half2* dst; int r;
    if (i < WQ4) { src = wq; dst = oq; r = i; }
    else if (i < WQ4 + WP4) { src = wp; dst = op; r = i - WQ4; }
    else if (i < WQ4 + WP4 + W14) { src = w1; dst = o1; r = i - WQ4 - WP4; }
    else if (i < WQ4 + WP4 + W14 + W24) { src = w2; dst = o2; r = i - WQ4 - WP4 - W14; }
    else return;
    float4 v = src[r];
    dst[2 * r]     = __floats2half2_rn(v.x, v.y);
    dst[2 * r + 1] = __floats2half2_rn(v.z, v.w);
}

// ---------------- LayerNorm (fp32 in, fp16 out) ----------------
__global__ __launch_bounds__(256) void ln_kernel(
    const float* __restrict__ x, const float* __restrict__ g,
    const float* __restrict__ b, __half* __restrict__ out)
{
    int row = blockIdx.x;
    const float* xr = x + (size_t)row * D_EMB;
    float sum = 0.f, sq = 0.f;
    for (int i = threadIdx.x; i < D_EMB; i += 256) {
        float v = xr[i]; sum += v; sq += v * v;
    }
    __shared__ float s1[8], s2[8];
    #pragma unroll
    for (int o = 16; o > 0; o >>= 1) {
        sum += __shfl_down_sync(0xffffffffu, sum, o);
        sq  += __shfl_down_sync(0xffffffffu, sq, o);
    }
    int w = threadIdx.x >> 5, l = threadIdx.x & 31;
    if (l == 0) { s1[w] = sum; s2[w] = sq; }
    __syncthreads();
    if (threadIdx.x == 0) {
        float a = 0.f, c = 0.f;
        #pragma unroll
        for (int i = 0; i < 8; i++) { a += s1[i]; c += s2[i]; }
        s1[0] = a * (1.0f / D_EMB);
        s2[0] = c * (1.0f / D_EMB);
    }
    __syncthreads();
    float mu = s1[0];
    float rstd = rsqrtf(s2[0] - mu * mu + 1e-6f);
    __half* orow = out + (size_t)row * D_EMB;
    for (int i = threadIdx.x; i < D_EMB; i += 256)
        orow[i] = __float2half_rn((xr[i] - mu) * rstd * g[i] + b[i]);
}

// ---------------- fp16 mma GEMM: C[M,N] = A[M,K]*B[N,K]^T + epilogue ----
// 128x128x64 CTA tile, 8 warps (2x4), warp tile 64x32, 2-stage double buffer,
// ONE __syncthreads per mainloop iter, ldmatrix.x4 fragment loads.
// smem row = 128 rows x 128 B; 16B chunk c stored at c ^ (r & 7).
#define TILE_BYTES  16384u
#define STAGE_BYTES 32768u
template <int MODE>
__global__ __launch_bounds__(256, 2) void mma_gemm_h(
    const __half* __restrict__ A, const __half* __restrict__ B,
    const float* __restrict__ bias, const float* __restrict__ res,
    void* __restrict__ Cout, int M, int N, int K)
{
    extern __shared__ char smc[];
    const uint32_t sbase = s2u(smc);
    const int tid = threadIdx.x, wid = tid >> 5, lane = tid & 31;
    const int g = lane >> 2, t = lane & 3;
    const int wm = wid >> 2, wn = wid & 3;
    const int m0 = blockIdx.y * 128, n0 = blockIdx.x * 128;
    const int NC = K >> 6;

    const __half* Agb = A + (size_t)m0 * K;
    const __half* Bgb = B + (size_t)n0 * K;

    float acc[4][4][4];
    #pragma unroll
    for (int i = 0; i < 4; i++)
        #pragma unroll
        for (int j = 0; j < 4; j++)
            #pragma unroll
            for (int q = 0; q < 4; q++) acc[i][j][q] = 0.f;

    // ldmatrix addresses: row&7 == lane&7 for every fragment row.
    const uint32_t lx = (uint32_t)(lane & 7);
    // A: row_i = wm*64 + i*16 + ((lane>>3)&1)*8 + (lane&7); chunk = 2ks + (lane>>4)
    uint32_t aRow[4];
    #pragma unroll
    for (int i = 0; i < 4; i++)
        aRow[i] = (uint32_t)((wm * 64 + i * 16 + ((lane >> 3) & 1) * 8 + (lane & 7)) * 128);
    uint32_t coA[4], coB[4];
    #pragma unroll
    for (int ks = 0; ks < 4; ks++) {
        coA[ks] = (((uint32_t)(2 * ks) + (uint32_t)(lane >> 4)) ^ lx) << 4;
        coB[ks] = (((uint32_t)(2 * ks) + (uint32_t)((lane >> 3) & 1)) ^ lx) << 4;
    }
    // B: row_p = wn*32 + 16p + (lane>>4)*8 + (lane&7)
    uint32_t bRow[2];
    #pragma unroll
    for (int p = 0; p < 2; p++)
        bRow[p] = (uint32_t)((wn * 32 + 16 * p + (lane >> 4) * 8 + (lane & 7)) * 128);

    auto load_tile = [&](int kc, int s) {
        uint32_t sa = sbase + (uint32_t)s * STAGE_BYTES;
        uint32_t sb = sa + TILE_BYTES;
        const __half* Ap = Agb + (size_t)kc * 64;
        const __half* Bp = Bgb + (size_t)kc * 64;
        #pragma unroll
        for (int q = 0; q < 4; q++) {
            int it = tid + q * 256;            // 0..1023
            int r = it >> 3, c = it & 7;
            uint32_t off = (uint32_t)(r * 128) + (((uint32_t)c ^ (uint32_t)(r & 7)) << 4);
            cp_async16(sa + off, Ap + (size_t)r * K + c * 8);
            cp_async16(sb + off, Bp + (size_t)r * K + c * 8);
        }
        CP_COMMIT();
    };

    load_tile(0, 0);

    for (int c = 0; c < NC; c++) {
        const int cur = c & 1;
        CP_WAIT(0);
        __syncthreads();
        if (c + 1 < NC) load_tile(c + 1, cur ^ 1);

        const uint32_t ab = sbase + (uint32_t)cur * STAGE_BYTES;
        const uint32_t bb = ab + TILE_BYTES;

        #pragma unroll
        for (int ks = 0; ks < 4; ks++) {
            uint32_t afr[4][4];
            #pragma unroll
            for (int i = 0; i < 4; i++)
                ldsm_x4(afr[i], ab + aRow[i] + coA[ks]);
            uint32_t bq[2][4];
            ldsm_x4(bq[0], bb + bRow[0] + coB[ks]);
            ldsm_x4(bq[1], bb + bRow[1] + coB[ks]);
            #pragma unroll
            for (int i = 0; i < 4; i++) {
                #pragma unroll
                for (int j = 0; j < 4; j++)
                    mma_f16(acc[i][j], afr[i], &bq[j >> 1][(j & 1) * 2]);
            }
        }
    }

    // epilogue
    #pragma unroll
    for (int i = 0; i < 4; i++) {
        const int r0 = m0 + wm * 64 + i * 16 + g;
        #pragma unroll
        for (int j = 0; j < 4; j++) {
            const int cc = n0 + wn * 32 + j * 8 + 2 * t;
            float2 bv = *(const float2*)(bias + cc);
            float v00 = acc[i][j][0] + bv.x, v01 = acc[i][j][1] + bv.y;
            float v10 = acc[i][j][2] + bv.x, v11 = acc[i][j][3] + bv.y;
            if (MODE == 1) {
                float2 r0v = *(const float2*)(res + (size_t)r0 * N + cc);
                float2 r1v = *(const float2*)(res + (size_t)(r0 + 8) * N + cc);
                v00 += r0v.x; v01 += r0v.y; v10 += r1v.x; v11 += r1v.y;
            }
            if (MODE == 2) {
                v00 = 0.5f * v00 * (1.0f + erff(v00 * 0.70710678118654752f));
                v01 = 0.5f * v01 * (1.0f + erff(v01 * 0.70710678118654752f));
                v10 = 0.5f * v10 * (1.0f + erff(v10 * 0.70710678118654752f));
                v11 = 0.5f * v11 * (1.0f + erff(v11 * 0.70710678118654752f));
            }
            if (MODE == 1) {
                float* Cf = (float*)Cout;
                *(float2*)(Cf + (size_t)r0 * N + cc)       = make_float2(v00, v01);
                *(float2*)(Cf + (size_t)(r0 + 8) * N + cc) = make_float2(v10, v11);
            } else {
                __half* Ch = (__half*)Cout;
                *(__half2*)(Ch + (size_t)r0 * N + cc)       = __floats2half2_rn(v00, v01);
                *(__half2*)(Ch + (size_t)(r0 + 8) * N + cc) = __floats2half2_rn(v10, v11);
            }
        }
    }
}

// ---------------- Flash attention via mma.sync (unchanged from R5) ----------
#define VT_STRIDE 72
__global__ __launch_bounds__(256) void attn_mma_kernel(
    const __half* __restrict__ qkv, __half* __restrict__ ctx)
{
    __shared__ __align__(16) char sQ[16384];
    __shared__ __align__(16) char sK[2][8192];
    __shared__ __align__(4)  __half sVt[64 * VT_STRIDE];

    const int tid = threadIdx.x, wid = tid >> 5, lane = tid & 31;
    const int g = lane >> 2, t = lane & 3;
    const int bh = blockIdx.y, b = bh / N_HEAD, h = bh % N_HEAD;
    const int q0 = blockIdx.x * 128;
    const size_t tok_base = (size_t)b * N_SEQ;
    const int hoff = h * HD;
    const uint32_t uQ = s2u(sQ), uVt = s2u(sVt);

    #pragma unroll
    for (int qi = 0; qi < 4; qi++) {
        int it = tid + qi * 256, r = it >> 3, c = it & 7;
        cp_async16(uQ + (uint32_t)(r * 128 + ((c ^ (r & 7)) * 16)),
                   qkv + (tok_base + q0 + r) * 2304 + hoff + c * 8);
    }
    {
        uint32_t uK0 = s2u(sK[0]);
        #pragma unroll
        for (int qi = 0; qi < 2; qi++) {
            int it = tid + qi * 256, r = it >> 3, c = it & 7;
            cp_async16(uK0 + (uint32_t)(r * 128 + ((c ^ (r & 7)) * 16)),
                       qkv + (tok_base + r) * 2304 + D_EMB + hoff + c * 8);
        }
    }
    CP_COMMIT();
    CP_WAIT(0);
    __syncthreads();

    uint32_t qf[4][4];
    {
        const int rq = wid * 16 + g;
        const __half2 s8 = __floats2half2_rn(0.125f, 0.125f);
        #pragma unroll
        for (int ks = 0; ks < 4; ks++) {
            uint32_t ca = (uint32_t)(((2 * ks) ^ (rq & 7)) * 16 + t * 4);
            uint32_t cb = (uint32_t)(((2 * ks + 1) ^ (rq & 7)) * 16 + t * 4);
            qf[ks][0] = lds32(uQ + rq * 128 + ca);
            qf[ks][1] = lds32(uQ + (rq + 8) * 128 + ca);
            qf[ks][2] = lds32(uQ + rq * 128 + cb);
            qf[ks][3] = lds32(uQ + (rq + 8) * 128 + cb);
            #pragma unroll
            for (int u = 0; u < 4; u++) {
                __half2 hv = *(__half2*)&qf[ks][u];
                hv = __hmul2(hv, s8);
                qf[ks][u] = *(uint32_t*)&hv;
            }
        }
    }

    float m_g = -1e30f, m_g8 = -1e30f, l_g = 0.f, l_g8 = 0.f;
    float of[8][4];
    #pragma unroll
    for (int j = 0; j < 8; j++)
        #pragma unroll
        for (int q = 0; q < 4; q++) of[j][q] = 0.f;

    const int vq = tid & 31, vd0 = (tid >> 5) * 8;

    for (int kt = 0; kt < N_SEQ / 64; kt++) {
        const float4 v0 = *(const float4*)(qkv + (tok_base + kt * 64 + 2 * vq) * 2304 + 2 * D_EMB + hoff + vd0);
        const float4 v1 = *(const float4*)(qkv + (tok_base + kt * 64 + 2 * vq + 1) * 2304 + 2 * D_EMB + hoff + vd0);

        if (kt > 0) CP_WAIT(0);
        __syncthreads();

        {
            const uint32_t* a0 = (const uint32_t*)&v0;
            const uint32_t* a1 = (const uint32_t*)&v1;
            #pragma unroll
            for (int u2 = 0; u2 < 4; u2++) {
                uint32_t lo = __byte_perm(a0[u2], a1[u2], 0x5410);
                uint32_t hi = __byte_perm(a0[u2], a1[u2], 0x7632);
                sts32(uVt + (uint32_t)((vd0 + 2 * u2) * (VT_STRIDE * 2) + 4 * vq), lo);
                sts32(uVt + (uint32_t)((vd0 + 2 * u2 + 1) * (VT_STRIDE * 2) + 4 * vq), hi);
            }
        }
        if (kt + 1 < N_SEQ / 64) {
            uint32_t uKn = s2u(sK[(kt + 1) & 1]);
            #pragma unroll
            for (int qi = 0; qi < 2; qi++) {
                int it = tid + qi * 256, r = it >> 3, c = it & 7;
                cp_async16(uKn + (uint32_t)(r * 128 + ((c ^ (r & 7)) * 16)),
                           qkv + (tok_base + (kt + 1) * 64 + r) * 2304 + D_EMB + hoff + c * 8);
            }
            CP_COMMIT();
        }
        __syncthreads();

        const uint32_t uKb = s2u(sK[kt & 1]);
        float sf[8][4];
        #pragma unroll
        for (int j = 0; j < 8; j++) {
            sf[j][0] = sf[j][1] = sf[j][2] = sf[j][3] = 0.f;
            const int rk = j * 8 + g;
            #pragma unroll
            for (int ks = 0; ks < 4; ks++) {
                uint32_t bb[2];
                bb[0] = lds32(uKb + rk * 128 + (uint32_t)((((2 * ks)     ^ (rk & 7)) * 16) + t * 4));
                bb[1] = lds32(uKb + rk * 128 + (uint32_t)((((2 * ks + 1) ^ (rk & 7)) * 16) + t * 4));
                mma_f16(sf[j], qf[ks], bb);
            }
        }

        float mg = m_g, mg8 = m_g8;
        #pragma unroll
        for (int j = 0; j < 8; j++) {
            mg  = fmaxf(mg,  fmaxf(sf[j][0], sf[j][1]));
            mg8 = fmaxf(mg8, fmaxf(sf[j][2], sf[j][3]));
        }
        mg  = fmaxf(mg,  __shfl_xor_sync(0xffffffffu, mg, 1));
        mg  = fmaxf(mg,  __shfl_xor_sync(0xffffffffu, mg, 2));
        mg8 = fmaxf(mg8, __shfl_xor_sync(0xffffffffu, mg8, 1));
        mg8 = fmaxf(mg8, __shfl_xor_sync(0xffffffffu, mg8, 2));
        const float alpha_g = __expf(m_g - mg), alpha_g8 = __expf(m_g8 - mg8);
        m_g = mg; m_g8 = mg8;

        float sl_g = 0.f, sl_g8 = 0.f;
        #pragma unroll
        for (int j = 0; j < 8; j++) {
            sf[j][0] = __expf(sf[j][0] - mg);
            sf[j][1] = __expf(sf[j][1] - mg);
            sf[j][2] = __expf(sf[j][2] - mg8);
            sf[j][3] = __expf(sf[j][3] - mg8);
            sl_g  += sf[j][0] + sf[j][1];
            sl_g8 += sf[j][2] + sf[j][3];
        }
        sl_g  += __shfl_xor_sync(0xffffffffu, sl_g, 1);
        sl_g  += __shfl_xor_sync(0xffffffffu, sl_g, 2);
        sl_g8 += __shfl_xor_sync(0xffffffffu, sl_g8, 1);
        sl_g8 += __shfl_xor_sync(0xffffffffu, sl_g8, 2);
        l_g  = l_g  * alpha_g  + sl_g;
        l_g8 = l_g8 * alpha_g8 + sl_g8;

        uint32_t pf[4][4];
        #pragma unroll
        for (int kp = 0; kp < 4; kp++) {
            pf[kp][0] = h2u(sf[2 * kp][0],     sf[2 * kp][1]);
            pf[kp][1] = h2u(sf[2 * kp][2],     sf[2 * kp][3]);
            pf[kp][2] = h2u(sf[2 * kp + 1][0], sf[2 * kp + 1][1]);
            pf[kp][3] = h2u(sf[2 * kp + 1][2], sf[2 * kp + 1][3]);
        }

        #pragma unroll
        for (int jd = 0; jd < 8; jd++) {
            of[jd][0] *= alpha_g;  of[jd][1] *= alpha_g;
            of[jd][2] *= alpha_g8; of[jd][3] *= alpha_g8;
            const uint32_t vrow = uVt + (uint32_t)((8 * jd + g) * (VT_STRIDE * 2));
            #pragma unroll
            for (int kp = 0; kp < 4; kp++) {
                uint32_t bb[2];
                bb[0] = lds32(vrow + (uint32_t)((16 * kp + 2 * t) * 2));
                bb[1] = lds32(vrow + (uint32_t)((16 * kp + 2 * t + 8) * 2));
                mma_f16(of[jd], pf[kp], bb);
            }
        }
    }

    const float il_g = 1.0f / l_g, il_g8 = 1.0f / l_g8;
    const int rq = wid * 16 + g;
    #pragma unroll
    for (int jd = 0; jd < 8; jd++) {
        const int col = hoff + 8 * jd + 2 * t;
        *(__half2*)(ctx + (tok_base + q0 + rq) * D_EMB + col) =
            __floats2half2_rn(of[jd][0] * il_g, of[jd][1] * il_g);
        *(__half2*)(ctx + (tok_base + q0 + rq + 8) * D_EMB + col) =
            __floats2half2_rn(of[jd][2] * il_g8, of[jd][3] * il_g8);
    }
}

// ---------------- host launcher ----------------
extern "C" void kernel_launch(void* const* d_in, const int* in_sizes, int n_in,
                              void* d_out, int out_size)
{
    const float* x      = (const float*)d_in[0];
    const float* ln1_g  = (const float*)d_in[1];
    const float* ln1_b  = (const float*)d_in[2];
    const float* qkv_w  = (const float*)d_in[3];
    const float* qkv_b  = (const float*)d_in[4];
    const float* proj_w = (const float*)d_in[5];
    const float* proj_b = (const float*)d_in[6];
    const float* ln2_g  = (const float*)d_in[7];
    const float* ln2_b  = (const float*)d_in[8];
    const float* fc1_w  = (const float*)d_in[9];
    const float* fc1_b  = (const float*)d_in[10];
    const float* fc2_w  = (const float*)d_in[11];
    const float* fc2_b  = (const float*)d_in[12];
    float* out = (float*)d_out;

    __half *p_xn, *p_qkv, *p_ctx, *p_h, *p_wq, *p_wp, *p_w1, *p_w2;
    float *p_x1;
    cudaGetSymbolAddress((void**)&p_xn,  g_xn);
    cudaGetSymbolAddress((void**)&p_qkv, g_qkv);
    cudaGetSymbolAddress((void**)&p_ctx, g_ctx);
    cudaGetSymbolAddress((void**)&p_x1,  g_x1);
    cudaGetSymbolAddress((void**)&p_h,   g_h);
    cudaGetSymbolAddress((void**)&p_wq,  g_wq);
    cudaGetSymbolAddress((void**)&p_wp,  g_wp);
    cudaGetSymbolAddress((void**)&p_w1,  g_w1);
    cudaGetSymbolAddress((void**)&p_w2,  g_w2);

    const int gemm_smem = 2 * (int)STAGE_BYTES;   // 65536 B
    cudaFuncSetAttribute(mma_gemm_h<0>, cudaFuncAttributeMaxDynamicSharedMemorySize, gemm_smem);
    cudaFuncSetAttribute(mma_gemm_h<1>, cudaFuncAttributeMaxDynamicSharedMemorySize, gemm_smem);
    cudaFuncSetAttribute(mma_gemm_h<2>, cudaFuncAttributeMaxDynamicSharedMemorySize, gemm_smem);

    // 0. convert all weights to fp16 (single launch)
    {
        const int n4 = WQ4 + WP4 + W14 + W24;
        prep_w_kernel<<<(n4 + 255) / 256, 256>>>(
            (const float4*)qkv_w, (const float4*)proj_w,
            (const float4*)fc1_w, (const float4*)fc2_w,
            (__half2*)p_wq, (__half2*)p_wp, (__half2*)p_w1, (__half2*)p_w2);
    }

    // 1. LN1 -> half
    ln_kernel<<<T_TOK, 256>>>(x, ln1_g, ln1_b, p_xn);
    // 2. QKV = xn @ qkv_w^T + b  -> half
    mma_gemm_h<0><<<dim3(2304 / 128, T_TOK / 128), 256, gemm_smem>>>(
        p_xn, p_wq, qkv_b, nullptr, p_qkv, T_TOK, 2304, D_EMB);
    // 3. flash attention (tensor-core) -> half ctx
    attn_mma_kernel<<<dim3(N_SEQ / 128, N_BATCH * N_HEAD), 256>>>(p_qkv, p_ctx);
    // 4. x1 = x + ctx @ proj_w^T + proj_b  -> fp32
    mma_gemm_h<1><<<dim3(D_EMB / 128, T_TOK / 128), 256, gemm_smem>>>(
        p_ctx, p_wp, proj_b, x, p_x1, T_TOK, D_EMB, D_EMB);
    // 5. LN2 -> half
    ln_kernel<<<T_TOK, 256>>>(p_x1, ln2_g, ln2_b, p_xn);
    // 6. h = gelu(xn @ fc1_w^T + fc1_b) -> half
    mma_gemm_h<2><<<dim3(D_HID / 128, T_TOK / 128), 256, gemm_smem>>>(
        p_xn, p_w1, fc1_b, nullptr, p_h, T_TOK, D_HID, D_EMB);
    // 7. out = x1 + h @ fc2_w^T + fc2_b  -> fp32
    mma_gemm_h<1><<<dim3(D_EMB / 128, T_TOK / 128), 256, gemm_smem>>>(
        p_h, p_w2, fc2_b, p_x1, out, T_TOK, D_EMB, D_HID);
}